// round 7
// baseline (speedup 1.0000x reference)
#include <cuda_runtime.h>

#define NN 100000
#define EE 1600000
#define F  128

// ---------------- device scratch (no allocations allowed) ----------------
__device__ __align__(16) float g_bufA[(size_t)NN * F];   // 51.2 MB
__device__ __align__(16) float g_bufB[(size_t)NN * F];   // 51.2 MB
__device__ float g_dinv[NN];
__device__ int   g_cnt[NN];
__device__ int   g_rowptr[NN + 1];
__device__ int   g_cursor[NN];
__device__ int   g_col[EE];
__device__ int   g_bsums[128];
__device__ int   g_is64;

// read edge index element (handles int32 or int64 storage)
__device__ __forceinline__ int ld_idx(const void* ei, size_t pos) {
    if (g_is64) return (int)((const long long*)ei)[pos];
    return ((const int*)ei)[pos];
}

// ---------------- dtype detect ----------------
__global__ void k_detect(const int* __restrict__ ei32) {
    __shared__ int nz;
    if (threadIdx.x == 0) nz = 0;
    __syncthreads();
    if (ei32[2 * threadIdx.x + 1] != 0) atomicOr(&nz, 1);
    __syncthreads();
    if (threadIdx.x == 0) g_is64 = (nz == 0) ? 1 : 0;
}

// ---------------- CSR build ----------------
__global__ void k_zero() {
    int i = blockIdx.x * blockDim.x + threadIdx.x;
    if (i < NN) g_cnt[i] = 0;
}

__global__ void k_hist(const void* __restrict__ ei) {
    int e = blockIdx.x * blockDim.x + threadIdx.x;
    if (e < EE) {
        int d = ld_idx(ei, (size_t)EE + e);
        atomicAdd(&g_cnt[d], 1);
    }
}

__global__ void k_dinv() {
    int i = blockIdx.x * blockDim.x + threadIdx.x;
    if (i < NN) g_dinv[i] = rsqrtf((float)(g_cnt[i] + 1));  // +1 self loop
}

__global__ void k_scan1() {
    __shared__ int s[1024];
    int t = threadIdx.x;
    int idx = blockIdx.x * 1024 + t;
    int v = (idx < NN) ? g_cnt[idx] : 0;
    s[t] = v;
    __syncthreads();
    for (int off = 1; off < 1024; off <<= 1) {
        int add = (t >= off) ? s[t - off] : 0;
        __syncthreads();
        s[t] += add;
        __syncthreads();
    }
    if (idx < NN) g_rowptr[idx] = s[t] - v;          // exclusive within block
    if (t == 1023) g_bsums[blockIdx.x] = s[t];       // block total
}

__global__ void k_scan2(int nb) {
    if (threadIdx.x == 0 && blockIdx.x == 0) {
        int run = 0;
        for (int b = 0; b < nb; b++) { int t = g_bsums[b]; g_bsums[b] = run; run += t; }
    }
}

__global__ void k_scan3() {
    int i = blockIdx.x * blockDim.x + threadIdx.x;
    if (i < NN) {
        int v = g_rowptr[i] + g_bsums[i >> 10];
        g_rowptr[i] = v;
        g_cursor[i] = v;
    }
    if (i == 0) g_rowptr[NN] = EE;
}

__global__ void k_fill(const void* __restrict__ ei) {
    int e = blockIdx.x * blockDim.x + threadIdx.x;
    if (e < EE) {
        int d = ld_idx(ei, (size_t)EE + e);
        int s = ld_idx(ei, (size_t)e);
        int p = atomicAdd(&g_cursor[d], 1);
        g_col[p] = s;
    }
}

// ---------------- GEMM: g_bufA[row] = dinv[row] * (in[row] @ W) ----------------
// 256 threads/block, 32 rows/block (4 rows/warp). W held in smem in two
// 64-row halves (32 KB) + X tile (16 KB) = 48 KB static shared.
__global__ void k_gemm(const float* __restrict__ xext, const float* __restrict__ W) {
    __shared__ float sW[64 * F];   // 32 KB (one K-half of W)
    __shared__ float sX[32 * F];   // 16 KB
    const float* in = xext ? xext : g_bufB;
    int tid = threadIdx.x;
    int rowBase = blockIdx.x * 32;
    {
        const float4* a = (const float4*)in;
#pragma unroll
        for (int i = 0; i < 4; i++) {
            int idx = tid + 256 * i;
            int r = rowBase + (idx >> 5);
            float4 v = make_float4(0.f, 0.f, 0.f, 0.f);
            if (r < NN) v = a[(size_t)r * 32 + (idx & 31)];
            ((float4*)sX)[idx] = v;
        }
    }
    int warp = tid >> 5, lane = tid & 31;
    float4 acc[4];
#pragma unroll
    for (int r = 0; r < 4; r++) acc[r] = make_float4(0.f, 0.f, 0.f, 0.f);

    for (int h = 0; h < 2; h++) {
        __syncthreads();   // guards sX (h=0) and prior sW reads (h=1)
        {
            const float4* w4 = (const float4*)(W + h * 64 * F);
#pragma unroll
            for (int i = 0; i < 8; i++) ((float4*)sW)[tid + 256 * i] = w4[tid + 256 * i];
        }
        __syncthreads();
        const float* xr = sX + (warp * 4) * F + h * 64;
#pragma unroll 4
        for (int k = 0; k < 64; k++) {
            float4 wv = ((const float4*)(sW + k * F))[lane];
#pragma unroll
            for (int r = 0; r < 4; r++) {
                float xv = xr[r * F + k];
                acc[r].x = fmaf(xv, wv.x, acc[r].x);
                acc[r].y = fmaf(xv, wv.y, acc[r].y);
                acc[r].z = fmaf(xv, wv.z, acc[r].z);
                acc[r].w = fmaf(xv, wv.w, acc[r].w);
            }
        }
    }
#pragma unroll
    for (int r = 0; r < 4; r++) {
        int row = rowBase + warp * 4 + r;
        if (row < NN) {
            float s = g_dinv[row];
            float4 v = acc[r];
            v.x *= s; v.y *= s; v.z *= s; v.w *= s;
            ((float4*)g_bufA)[(size_t)row * 32 + lane] = v;
        }
    }
}

// ---------------- aggregation: bufB[i] = relu(dinv[i]*(bufA[i] + sum bufA[nbr]) + b) ----------------
// one warp per node, float4 per lane, 4x unrolled edge loop for MLP=4
__global__ void k_agg(const float* __restrict__ bias) {
    int w = (blockIdx.x * blockDim.x + threadIdx.x) >> 5;
    int lane = threadIdx.x & 31;
    if (w >= NN) return;
    const float4* g4 = (const float4*)g_bufA;
    float4 acc = g4[(size_t)w * 32 + lane];   // self loop term
    int s = g_rowptr[w], e = g_rowptr[w + 1];
    int p = s;
    for (; p + 4 <= e; p += 4) {
        int j0 = g_col[p];
        int j1 = g_col[p + 1];
        int j2 = g_col[p + 2];
        int j3 = g_col[p + 3];
        float4 v0 = g4[(size_t)j0 * 32 + lane];
        float4 v1 = g4[(size_t)j1 * 32 + lane];
        float4 v2 = g4[(size_t)j2 * 32 + lane];
        float4 v3 = g4[(size_t)j3 * 32 + lane];
        acc.x += (v0.x + v1.x) + (v2.x + v3.x);
        acc.y += (v0.y + v1.y) + (v2.y + v3.y);
        acc.z += (v0.z + v1.z) + (v2.z + v3.z);
        acc.w += (v0.w + v1.w) + (v2.w + v3.w);
    }
    for (; p < e; p++) {
        int j = g_col[p];
        float4 v = g4[(size_t)j * 32 + lane];
        acc.x += v.x; acc.y += v.y; acc.z += v.z; acc.w += v.w;
    }
    float di = g_dinv[w];
    float4 b = ((const float4*)bias)[lane];
    float4 o;
    o.x = fmaxf(fmaf(acc.x, di, b.x), 0.f);
    o.y = fmaxf(fmaf(acc.y, di, b.y), 0.f);
    o.z = fmaxf(fmaf(acc.z, di, b.z), 0.f);
    o.w = fmaxf(fmaf(acc.w, di, b.w), 0.f);
    ((float4*)g_bufB)[(size_t)w * 32 + lane] = o;
}

// ---------------- fused heads (reads g_bufB) ----------------
// pos = relu(h@Wp1+bp1)@Wp2 + bp2 ; time = relu(h@Wt1+bt1)@Wt2 + bt2
// 256 threads/block, 32 rows/block. Weights streamed in K-quarters:
// sX 16KB + sWp 16KB + sWt 8KB = 40 KB static shared.
__global__ void k_head(const float* __restrict__ Wp1, const float* __restrict__ bp1,
                       const float* __restrict__ Wp2, const float* __restrict__ bp2,
                       const float* __restrict__ Wt1, const float* __restrict__ bt1,
                       const float* __restrict__ Wt2, const float* __restrict__ bt2,
                       float* __restrict__ out) {
    __shared__ float sX[32 * F];    // 16 KB
    __shared__ float sWp[32 * F];   // 16 KB (K-quarter of Wp1)
    __shared__ float sWt[32 * 64];  // 8 KB  (K-quarter of Wt1)
    int tid = threadIdx.x;
    int rowBase = blockIdx.x * 32;
    {
        const float4* a = (const float4*)g_bufB;
#pragma unroll
        for (int i = 0; i < 4; i++) {
            int idx = tid + 256 * i;
            int r = rowBase + (idx >> 5);
            float4 v = make_float4(0.f, 0.f, 0.f, 0.f);
            if (r < NN) v = a[(size_t)r * 32 + (idx & 31)];
            ((float4*)sX)[idx] = v;
        }
    }
    int warp = tid >> 5, lane = tid & 31;
    float4 accp[4];
    float2 acct[4];
#pragma unroll
    for (int r = 0; r < 4; r++) {
        accp[r] = make_float4(0.f, 0.f, 0.f, 0.f);
        acct[r] = make_float2(0.f, 0.f);
    }

    for (int q = 0; q < 4; q++) {
        __syncthreads();
        {
            const float4* wp4 = (const float4*)(Wp1 + q * 32 * F);
#pragma unroll
            for (int i = 0; i < 4; i++) ((float4*)sWp)[tid + 256 * i] = wp4[tid + 256 * i];
            const float4* wt4 = (const float4*)(Wt1 + q * 32 * 64);
#pragma unroll
            for (int i = 0; i < 2; i++) ((float4*)sWt)[tid + 256 * i] = wt4[tid + 256 * i];
        }
        __syncthreads();
        const float* xr = sX + (warp * 4) * F + q * 32;
#pragma unroll 4
        for (int k = 0; k < 32; k++) {
            float4 wp = ((const float4*)(sWp + k * F))[lane];
            float2 wt = ((const float2*)(sWt + k * 64))[lane];
#pragma unroll
            for (int r = 0; r < 4; r++) {
                float xv = xr[r * F + k];
                accp[r].x = fmaf(xv, wp.x, accp[r].x);
                accp[r].y = fmaf(xv, wp.y, accp[r].y);
                accp[r].z = fmaf(xv, wp.z, accp[r].z);
                accp[r].w = fmaf(xv, wp.w, accp[r].w);
                acct[r].x = fmaf(xv, wt.x, acct[r].x);
                acct[r].y = fmaf(xv, wt.y, acct[r].y);
            }
        }
    }

    // epilogue: per-lane second-layer weights, warp reduce
    float4 bP = ((const float4*)bp1)[lane];
    float2 bT = ((const float2*)bt1)[lane];
    float wp2a[4], wp2b[4];
#pragma unroll
    for (int i = 0; i < 4; i++) {
        wp2a[i] = Wp2[(lane * 4 + i) * 2];
        wp2b[i] = Wp2[(lane * 4 + i) * 2 + 1];
    }
    float wt2_0 = Wt2[lane * 2], wt2_1 = Wt2[lane * 2 + 1];
    float bpos0 = bp2[0], bpos1 = bp2[1], btime = bt2[0];

#pragma unroll
    for (int r = 0; r < 4; r++) {
        int row = rowBase + warp * 4 + r;
        float p0 = fmaxf(accp[r].x + bP.x, 0.f);
        float p1 = fmaxf(accp[r].y + bP.y, 0.f);
        float p2 = fmaxf(accp[r].z + bP.z, 0.f);
        float p3 = fmaxf(accp[r].w + bP.w, 0.f);
        float t0 = fmaxf(acct[r].x + bT.x, 0.f);
        float t1 = fmaxf(acct[r].y + bT.y, 0.f);
        float px = p0 * wp2a[0] + p1 * wp2a[1] + p2 * wp2a[2] + p3 * wp2a[3];
        float py = p0 * wp2b[0] + p1 * wp2b[1] + p2 * wp2b[2] + p3 * wp2b[3];
        float tv = t0 * wt2_0 + t1 * wt2_1;
#pragma unroll
        for (int off = 16; off; off >>= 1) {
            px += __shfl_down_sync(0xffffffffu, px, off);
            py += __shfl_down_sync(0xffffffffu, py, off);
            tv += __shfl_down_sync(0xffffffffu, tv, off);
        }
        if (lane == 0 && row < NN) {
            out[(size_t)row * 3 + 0] = px + bpos0;
            out[(size_t)row * 3 + 1] = py + bpos1;
            out[(size_t)row * 3 + 2] = tv + btime;
        }
    }
}

// ---------------- launch ----------------
extern "C" void kernel_launch(void* const* d_in, const int* in_sizes, int n_in,
                              void* d_out, int out_size) {
    const float* x   = (const float*)d_in[0];
    const void*  ei  = d_in[1];
    const float* W1  = (const float*)d_in[2];  const float* b1  = (const float*)d_in[3];
    const float* W2  = (const float*)d_in[4];  const float* b2  = (const float*)d_in[5];
    const float* W3  = (const float*)d_in[6];  const float* b3  = (const float*)d_in[7];
    const float* Wp1 = (const float*)d_in[8];  const float* bp1 = (const float*)d_in[9];
    const float* Wp2 = (const float*)d_in[10]; const float* bp2 = (const float*)d_in[11];
    const float* Wt1 = (const float*)d_in[12]; const float* bt1 = (const float*)d_in[13];
    const float* Wt2 = (const float*)d_in[14]; const float* bt2 = (const float*)d_in[15];
    float* out = (float*)d_out;

    int nb256  = (NN + 255) / 256;
    int ebl    = (EE + 255) / 256;
    int nbScan = (NN + 1023) / 1024;

    k_detect<<<1, 1024>>>((const int*)ei);
    k_zero<<<nb256, 256>>>();
    k_hist<<<ebl, 256>>>(ei);
    k_dinv<<<nb256, 256>>>();
    k_scan1<<<nbScan, 1024>>>();
    k_scan2<<<1, 1>>>(nbScan);
    k_scan3<<<nb256, 256>>>();
    k_fill<<<ebl, 256>>>(ei);

    int gemmGrid = (NN + 31) / 32;
    int aggGrid  = (NN + 7) / 8;   // 8 warps per 256-thread block, 1 warp per node

    k_gemm<<<gemmGrid, 256>>>(x, W1);
    k_agg <<<aggGrid, 256>>>(b1);
    k_gemm<<<gemmGrid, 256>>>(nullptr, W2);
    k_agg <<<aggGrid, 256>>>(b2);
    k_gemm<<<gemmGrid, 256>>>(nullptr, W3);
    k_agg <<<aggGrid, 256>>>(b3);

    k_head<<<gemmGrid, 256>>>(Wp1, bp1, Wp2, bp2, Wt1, bt1, Wt2, bt2, out);
}

// round 9
// speedup vs baseline: 1.2057x; 1.2057x over previous
#include <cuda_runtime.h>
#include <mma.h>

using namespace nvcuda;

#define NN 100000
#define EE 1600000
#define F  128

// ---------------- device scratch (no allocations allowed) ----------------
__device__ __align__(16) float g_bufA[(size_t)NN * F];   // 51.2 MB
__device__ __align__(16) float g_bufB[(size_t)NN * F];   // 51.2 MB
__device__ float g_dinv[NN];
__device__ int   g_cnt[NN];
__device__ int   g_rowptr[NN + 1];
__device__ int   g_cursor[NN];
__device__ int   g_col[EE];
__device__ int   g_bsums[128];
__device__ int   g_is64;

// read edge index element (handles int32 or int64 storage)
__device__ __forceinline__ int ld_idx(const void* ei, size_t pos) {
    if (g_is64) return (int)((const long long*)ei)[pos];
    return ((const int*)ei)[pos];
}

// ---------------- dtype detect ----------------
__global__ void k_detect(const int* __restrict__ ei32) {
    __shared__ int nz;
    if (threadIdx.x == 0) nz = 0;
    __syncthreads();
    if (ei32[2 * threadIdx.x + 1] != 0) atomicOr(&nz, 1);
    __syncthreads();
    if (threadIdx.x == 0) g_is64 = (nz == 0) ? 1 : 0;
}

// ---------------- CSR build ----------------
__global__ void k_zero() {
    int i = blockIdx.x * blockDim.x + threadIdx.x;
    if (i < NN) g_cnt[i] = 0;
}

__global__ void k_hist(const void* __restrict__ ei) {
    int e = blockIdx.x * blockDim.x + threadIdx.x;
    if (e < EE) {
        int d = ld_idx(ei, (size_t)EE + e);
        atomicAdd(&g_cnt[d], 1);
    }
}

__global__ void k_dinv() {
    int i = blockIdx.x * blockDim.x + threadIdx.x;
    if (i < NN) g_dinv[i] = rsqrtf((float)(g_cnt[i] + 1));  // +1 self loop
}

__global__ void k_scan1() {
    __shared__ int s[1024];
    int t = threadIdx.x;
    int idx = blockIdx.x * 1024 + t;
    int v = (idx < NN) ? g_cnt[idx] : 0;
    s[t] = v;
    __syncthreads();
    for (int off = 1; off < 1024; off <<= 1) {
        int add = (t >= off) ? s[t - off] : 0;
        __syncthreads();
        s[t] += add;
        __syncthreads();
    }
    if (idx < NN) g_rowptr[idx] = s[t] - v;          // exclusive within block
    if (t == 1023) g_bsums[blockIdx.x] = s[t];       // block total
}

__global__ void k_scan2(int nb) {
    if (threadIdx.x == 0 && blockIdx.x == 0) {
        int run = 0;
        for (int b = 0; b < nb; b++) { int t = g_bsums[b]; g_bsums[b] = run; run += t; }
    }
}

__global__ void k_scan3() {
    int i = blockIdx.x * blockDim.x + threadIdx.x;
    if (i < NN) {
        int v = g_rowptr[i] + g_bsums[i >> 10];
        g_rowptr[i] = v;
        g_cursor[i] = v;
    }
    if (i == 0) g_rowptr[NN] = EE;
}

__global__ void k_fill(const void* __restrict__ ei) {
    int e = blockIdx.x * blockDim.x + threadIdx.x;
    if (e < EE) {
        int d = ld_idx(ei, (size_t)EE + e);
        int s = ld_idx(ei, (size_t)e);
        int p = atomicAdd(&g_cursor[d], 1);
        g_col[p] = s;
    }
}

// ---------------- GEMM (3xTF32 via wmma, NO inline asm): ----------------
// g_bufA[row] = dinv[row] * (in[row] @ W)
// Block: 256 threads = 8 warps. 64 rows x 128 cols per block.
// Warp (wr = w>>1 in 0..3, wc = w&1 in 0..1): rows wr*16..+16, cols wc*64..+64
// = 4 accumulator tiles of m16n16. K streamed in chunks of 16 (2 k8-steps).
// smem: sAhi/sAlo 64x16, sBhi/sBlo 16x128 (24 KB); epilogue staging reuses 32 KB.
__global__ void k_gemm(const float* __restrict__ xext, const float* __restrict__ W) {
    __shared__ float smem[8192];   // 32 KB, aliased: chunks during loop, staging after
    float* sAhi = smem;            // 64*16
    float* sAlo = smem + 1024;
    float* sBhi = smem + 2048;     // 16*128
    float* sBlo = smem + 4096;

    const float* in = xext ? xext : g_bufB;
    int tid  = threadIdx.x;
    int warp = tid >> 5, lane = tid & 31;
    int wr = warp >> 1;            // 0..3
    int wc = warp & 1;             // 0..1
    int rowBase = blockIdx.x * 64;

    wmma::fragment<wmma::accumulator, 16, 16, 8, float> acc[4];
#pragma unroll
    for (int nt = 0; nt < 4; nt++) wmma::fill_fragment(acc[nt], 0.0f);

    for (int kc = 0; kc < 8; kc++) {
        __syncthreads();
        // stage A chunk: 64 rows x 16 cols, split hi/lo
#pragma unroll
        for (int i = 0; i < 4; i++) {
            int idx = tid + 256 * i;          // 0..1023
            int r = idx >> 4, c = idx & 15;
            int row = rowBase + r;
            float v = (row < NN) ? in[(size_t)row * F + kc * 16 + c] : 0.0f;
            float hi = wmma::__float_to_tf32(v);
            float lo = wmma::__float_to_tf32(v - hi);
            sAhi[idx] = hi;
            sAlo[idx] = lo;
        }
        // stage B chunk: 16 rows x 128 cols, split hi/lo
#pragma unroll
        for (int i = 0; i < 8; i++) {
            int idx = tid + 256 * i;          // 0..2047
            int k = idx >> 7, n = idx & 127;
            float v = W[(size_t)(kc * 16 + k) * F + n];
            float hi = wmma::__float_to_tf32(v);
            float lo = wmma::__float_to_tf32(v - hi);
            sBhi[idx] = hi;
            sBlo[idx] = lo;
        }
        __syncthreads();

#pragma unroll
        for (int k8 = 0; k8 < 2; k8++) {
            wmma::fragment<wmma::matrix_a, 16, 16, 8, wmma::precision::tf32, wmma::row_major> a_hi, a_lo;
            wmma::load_matrix_sync(a_hi, sAhi + (wr * 16) * 16 + k8 * 8, 16);
            wmma::load_matrix_sync(a_lo, sAlo + (wr * 16) * 16 + k8 * 8, 16);
#pragma unroll
            for (int nt = 0; nt < 4; nt++) {
                wmma::fragment<wmma::matrix_b, 16, 16, 8, wmma::precision::tf32, wmma::row_major> b_hi, b_lo;
                int boff = (k8 * 8) * 128 + wc * 64 + nt * 16;
                wmma::load_matrix_sync(b_hi, sBhi + boff, 128);
                wmma::load_matrix_sync(b_lo, sBlo + boff, 128);
                wmma::mma_sync(acc[nt], a_hi, b_hi, acc[nt]);   // hi*hi
                wmma::mma_sync(acc[nt], a_hi, b_lo, acc[nt]);   // hi*lo
                wmma::mma_sync(acc[nt], a_lo, b_hi, acc[nt]);   // lo*hi
            }
        }
    }

    // epilogue: stage accumulators to smem (per-warp 16x64), scale by dinv, store
    __syncthreads();
    float* stage = smem + warp * 1024;     // 16 rows x 64 cols
#pragma unroll
    for (int nt = 0; nt < 4; nt++)
        wmma::store_matrix_sync(stage + nt * 16, acc[nt], 64, wmma::mem_row_major);
    __syncwarp();
#pragma unroll
    for (int i = 0; i < 8; i++) {
        int idx = lane + 32 * i;            // 0..255 float4s
        int r = idx >> 4, c4 = idx & 15;
        int row = rowBase + wr * 16 + r;
        if (row < NN) {
            float s = g_dinv[row];
            float4 v = *(float4*)&stage[r * 64 + c4 * 4];
            v.x *= s; v.y *= s; v.z *= s; v.w *= s;
            *(float4*)&g_bufA[(size_t)row * F + wc * 64 + c4 * 4] = v;
        }
    }
}

// ---------------- aggregation: bufB[i] = relu(dinv[i]*(bufA[i] + sum bufA[nbr]) + b) ----------------
// one warp per node, float4 per lane (R3-exact: simple loop, MLP_p1 = 1)
__global__ void k_agg(const float* __restrict__ bias) {
    int w = (blockIdx.x * blockDim.x + threadIdx.x) >> 5;
    int lane = threadIdx.x & 31;
    if (w >= NN) return;
    const float4* g4 = (const float4*)g_bufA;
    float4 acc = g4[(size_t)w * 32 + lane];   // self loop term
    int s = g_rowptr[w], e = g_rowptr[w + 1];
    for (int p = s; p < e; p++) {
        int j = g_col[p];
        float4 v = g4[(size_t)j * 32 + lane];
        acc.x += v.x; acc.y += v.y; acc.z += v.z; acc.w += v.w;
    }
    float di = g_dinv[w];
    float4 b = ((const float4*)bias)[lane];
    float4 o;
    o.x = fmaxf(fmaf(acc.x, di, b.x), 0.f);
    o.y = fmaxf(fmaf(acc.y, di, b.y), 0.f);
    o.z = fmaxf(fmaf(acc.z, di, b.z), 0.f);
    o.w = fmaxf(fmaf(acc.w, di, b.w), 0.f);
    ((float4*)g_bufB)[(size_t)w * 32 + lane] = o;
}

// ---------------- fused heads (reads g_bufB) ----------------
__global__ void k_head(const float* __restrict__ Wp1, const float* __restrict__ bp1,
                       const float* __restrict__ Wp2, const float* __restrict__ bp2,
                       const float* __restrict__ Wt1, const float* __restrict__ bt1,
                       const float* __restrict__ Wt2, const float* __restrict__ bt2,
                       float* __restrict__ out) {
    __shared__ float sX[32 * F];    // 16 KB
    __shared__ float sWp[32 * F];   // 16 KB (K-quarter of Wp1)
    __shared__ float sWt[32 * 64];  // 8 KB  (K-quarter of Wt1)
    int tid = threadIdx.x;
    int rowBase = blockIdx.x * 32;
    {
        const float4* a = (const float4*)g_bufB;
#pragma unroll
        for (int i = 0; i < 4; i++) {
            int idx = tid + 256 * i;
            int r = rowBase + (idx >> 5);
            float4 v = make_float4(0.f, 0.f, 0.f, 0.f);
            if (r < NN) v = a[(size_t)r * 32 + (idx & 31)];
            ((float4*)sX)[idx] = v;
        }
    }
    int warp = tid >> 5, lane = tid & 31;
    float4 accp[4];
    float2 acct[4];
#pragma unroll
    for (int r = 0; r < 4; r++) {
        accp[r] = make_float4(0.f, 0.f, 0.f, 0.f);
        acct[r] = make_float2(0.f, 0.f);
    }

    for (int q = 0; q < 4; q++) {
        __syncthreads();
        {
            const float4* wp4 = (const float4*)(Wp1 + q * 32 * F);
#pragma unroll
            for (int i = 0; i < 4; i++) ((float4*)sWp)[tid + 256 * i] = wp4[tid + 256 * i];
            const float4* wt4 = (const float4*)(Wt1 + q * 32 * 64);
#pragma unroll
            for (int i = 0; i < 2; i++) ((float4*)sWt)[tid + 256 * i] = wt4[tid + 256 * i];
        }
        __syncthreads();
        const float* xr = sX + (warp * 4) * F + q * 32;
#pragma unroll 4
        for (int k = 0; k < 32; k++) {
            float4 wp = ((const float4*)(sWp + k * F))[lane];
            float2 wt = ((const float2*)(sWt + k * 64))[lane];
#pragma unroll
            for (int r = 0; r < 4; r++) {
                float xv = xr[r * F + k];
                accp[r].x = fmaf(xv, wp.x, accp[r].x);
                accp[r].y = fmaf(xv, wp.y, accp[r].y);
                accp[r].z = fmaf(xv, wp.z, accp[r].z);
                accp[r].w = fmaf(xv, wp.w, accp[r].w);
                acct[r].x = fmaf(xv, wt.x, acct[r].x);
                acct[r].y = fmaf(xv, wt.y, acct[r].y);
            }
        }
    }

    // epilogue: per-lane second-layer weights, warp reduce
    float4 bP = ((const float4*)bp1)[lane];
    float2 bT = ((const float2*)bt1)[lane];
    float wp2a[4], wp2b[4];
#pragma unroll
    for (int i = 0; i < 4; i++) {
        wp2a[i] = Wp2[(lane * 4 + i) * 2];
        wp2b[i] = Wp2[(lane * 4 + i) * 2 + 1];
    }
    float wt2_0 = Wt2[lane * 2], wt2_1 = Wt2[lane * 2 + 1];
    float bpos0 = bp2[0], bpos1 = bp2[1], btime = bt2[0];

#pragma unroll
    for (int r = 0; r < 4; r++) {
        int row = rowBase + warp * 4 + r;
        float p0 = fmaxf(accp[r].x + bP.x, 0.f);
        float p1 = fmaxf(accp[r].y + bP.y, 0.f);
        float p2 = fmaxf(accp[r].z + bP.z, 0.f);
        float p3 = fmaxf(accp[r].w + bP.w, 0.f);
        float t0 = fmaxf(acct[r].x + bT.x, 0.f);
        float t1 = fmaxf(acct[r].y + bT.y, 0.f);
        float px = p0 * wp2a[0] + p1 * wp2a[1] + p2 * wp2a[2] + p3 * wp2a[3];
        float py = p0 * wp2b[0] + p1 * wp2b[1] + p2 * wp2b[2] + p3 * wp2b[3];
        float tv = t0 * wt2_0 + t1 * wt2_1;
#pragma unroll
        for (int off = 16; off; off >>= 1) {
            px += __shfl_down_sync(0xffffffffu, px, off);
            py += __shfl_down_sync(0xffffffffu, py, off);
            tv += __shfl_down_sync(0xffffffffu, tv, off);
        }
        if (lane == 0 && row < NN) {
            out[(size_t)row * 3 + 0] = px + bpos0;
            out[(size_t)row * 3 + 1] = py + bpos1;
            out[(size_t)row * 3 + 2] = tv + btime;
        }
    }
}

// ---------------- launch ----------------
extern "C" void kernel_launch(void* const* d_in, const int* in_sizes, int n_in,
                              void* d_out, int out_size) {
    const float* x   = (const float*)d_in[0];
    const void*  ei  = d_in[1];
    const float* W1  = (const float*)d_in[2];  const float* b1  = (const float*)d_in[3];
    const float* W2  = (const float*)d_in[4];  const float* b2  = (const float*)d_in[5];
    const float* W3  = (const float*)d_in[6];  const float* b3  = (const float*)d_in[7];
    const float* Wp1 = (const float*)d_in[8];  const float* bp1 = (const float*)d_in[9];
    const float* Wp2 = (const float*)d_in[10]; const float* bp2 = (const float*)d_in[11];
    const float* Wt1 = (const float*)d_in[12]; const float* bt1 = (const float*)d_in[13];
    const float* Wt2 = (const float*)d_in[14]; const float* bt2 = (const float*)d_in[15];
    float* out = (float*)d_out;

    int nb256  = (NN + 255) / 256;
    int ebl    = (EE + 255) / 256;
    int nbScan = (NN + 1023) / 1024;

    k_detect<<<1, 1024>>>((const int*)ei);
    k_zero<<<nb256, 256>>>();
    k_hist<<<ebl, 256>>>(ei);
    k_dinv<<<nb256, 256>>>();
    k_scan1<<<nbScan, 1024>>>();
    k_scan2<<<1, 1>>>(nbScan);
    k_scan3<<<nb256, 256>>>();
    k_fill<<<ebl, 256>>>(ei);

    int gemmGrid = (NN + 63) / 64;     // 1563
    int aggGrid  = (NN + 7) / 8;       // 1 warp per node
    int headGrid = (NN + 31) / 32;

    k_gemm<<<gemmGrid, 256>>>(x, W1);
    k_agg <<<aggGrid, 256>>>(b1);
    k_gemm<<<gemmGrid, 256>>>(nullptr, W2);
    k_agg <<<aggGrid, 256>>>(b2);
    k_gemm<<<gemmGrid, 256>>>(nullptr, W3);
    k_agg <<<aggGrid, 256>>>(b3);

    k_head<<<headGrid, 256>>>(Wp1, bp1, Wp2, bp2, Wt1, bt1, Wt2, bt2, out);
}

// round 11
// speedup vs baseline: 1.3236x; 1.0978x over previous
#include <cuda_runtime.h>
#include <mma.h>

using namespace nvcuda;

#define NN 100000
#define EE 1600000
#define F  128

// ---------------- device scratch (no allocations allowed) ----------------
__device__ __align__(16) float g_bufA[(size_t)NN * F];   // 51.2 MB
__device__ __align__(16) float g_bufB[(size_t)NN * F];   // 51.2 MB
__device__ float g_dinv[NN];
__device__ int   g_cnt[NN];
__device__ int   g_rowptr[NN + 1];
__device__ int   g_cursor[NN];
__device__ int   g_col[EE];
__device__ int   g_bsums[128];
__device__ int   g_is64;

// read edge index element (handles int32 or int64 storage)
__device__ __forceinline__ int ld_idx(const void* ei, size_t pos) {
    if (g_is64) return (int)((const long long*)ei)[pos];
    return ((const int*)ei)[pos];
}

// ---------------- dtype detect ----------------
__global__ void k_detect(const int* __restrict__ ei32) {
    __shared__ int nz;
    if (threadIdx.x == 0) nz = 0;
    __syncthreads();
    if (ei32[2 * threadIdx.x + 1] != 0) atomicOr(&nz, 1);
    __syncthreads();
    if (threadIdx.x == 0) g_is64 = (nz == 0) ? 1 : 0;
}

// ---------------- CSR build ----------------
__global__ void k_zero() {
    int i = blockIdx.x * blockDim.x + threadIdx.x;
    if (i < NN) g_cnt[i] = 0;
}

__global__ void k_hist(const void* __restrict__ ei) {
    int e = blockIdx.x * blockDim.x + threadIdx.x;
    if (e < EE) {
        int d = ld_idx(ei, (size_t)EE + e);
        atomicAdd(&g_cnt[d], 1);
    }
}

__global__ void k_dinv() {
    int i = blockIdx.x * blockDim.x + threadIdx.x;
    if (i < NN) g_dinv[i] = rsqrtf((float)(g_cnt[i] + 1));  // +1 self loop
}

__global__ void k_scan1() {
    __shared__ int s[1024];
    int t = threadIdx.x;
    int idx = blockIdx.x * 1024 + t;
    int v = (idx < NN) ? g_cnt[idx] : 0;
    s[t] = v;
    __syncthreads();
    for (int off = 1; off < 1024; off <<= 1) {
        int add = (t >= off) ? s[t - off] : 0;
        __syncthreads();
        s[t] += add;
        __syncthreads();
    }
    if (idx < NN) g_rowptr[idx] = s[t] - v;          // exclusive within block
    if (t == 1023) g_bsums[blockIdx.x] = s[t];       // block total
}

__global__ void k_scan2(int nb) {
    if (threadIdx.x == 0 && blockIdx.x == 0) {
        int run = 0;
        for (int b = 0; b < nb; b++) { int t = g_bsums[b]; g_bsums[b] = run; run += t; }
    }
}

__global__ void k_scan3() {
    int i = blockIdx.x * blockDim.x + threadIdx.x;
    if (i < NN) {
        int v = g_rowptr[i] + g_bsums[i >> 10];
        g_rowptr[i] = v;
        g_cursor[i] = v;
    }
    if (i == 0) g_rowptr[NN] = EE;
}

__global__ void k_fill(const void* __restrict__ ei) {
    int e = blockIdx.x * blockDim.x + threadIdx.x;
    if (e < EE) {
        int d = ld_idx(ei, (size_t)EE + e);
        int s = ld_idx(ei, (size_t)e);
        int p = atomicAdd(&g_cursor[d], 1);
        g_col[p] = s;
    }
}

// ---------------- GEMM v2 (3xTF32 wmma, raw-fp32 staging + register split) ----
// g_bufA[row] = dinv[row] * (in[row] @ W)
// Block: 256 threads = 8 warps, 128 rows x 128 cols.
// Warp (wr = w>>1 in 0..3, wc = w&1): rows wr*32..+32 (2 m16 tiles), cols wc*64..+64 (4 n16 tiles).
// K streamed in chunks of 32. smem staged as RAW fp32 (padded ldm: A=40, B=136,
// both keep every fragment ptr 32B-aligned and de-stride the banks).
// hi/lo tf32 split: fragment loaded TWICE from the same smem (identical element
// mapping), then mutated elementwise in registers — no fragment copy-assign.
__global__ void k_gemm(const float* __restrict__ xext, const float* __restrict__ W) {
    __shared__ float smem[9472];          // 37 KB; aliased for epilogue staging
    float* sA = smem;                     // 128 x 40 (32 cols used)
    float* sB = smem + 5120;              // 32 x 136 (128 cols used)

    const float* in = xext ? xext : g_bufB;
    int tid  = threadIdx.x;
    int warp = tid >> 5, lane = tid & 31;
    int wr = warp >> 1;                   // 0..3
    int wc = warp & 1;                    // 0..1
    int rowBase = blockIdx.x * 128;

    wmma::fragment<wmma::accumulator, 16, 16, 8, float> acc[2][4];
#pragma unroll
    for (int mt = 0; mt < 2; mt++)
#pragma unroll
        for (int nt = 0; nt < 4; nt++) wmma::fill_fragment(acc[mt][nt], 0.0f);

    for (int kc = 0; kc < 4; kc++) {
        __syncthreads();
        // stage A chunk raw: 128 rows x 32 cols (1024 float4)
#pragma unroll
        for (int i = 0; i < 4; i++) {
            int idx = tid + 256 * i;
            int r = idx >> 3, c4 = idx & 7;
            int row = rowBase + r;
            float4 v = make_float4(0.f, 0.f, 0.f, 0.f);
            if (row < NN) v = ((const float4*)in)[(size_t)row * 32 + kc * 8 + c4];
            *(float4*)&sA[r * 40 + c4 * 4] = v;
        }
        // stage B chunk raw: 32 rows x 128 cols (1024 float4)
#pragma unroll
        for (int i = 0; i < 4; i++) {
            int idx = tid + 256 * i;
            int k = idx >> 5, c4 = idx & 31;
            float4 v = ((const float4*)W)[(size_t)(kc * 32 + k) * 32 + c4];
            *(float4*)&sB[k * 136 + c4 * 4] = v;
        }
        __syncthreads();

#pragma unroll
        for (int k8 = 0; k8 < 4; k8++) {
            // A fragments: load raw twice (same ptr/ldm => same mapping), split in regs
            wmma::fragment<wmma::matrix_a, 16, 16, 8, wmma::precision::tf32, wmma::row_major> a_hi[2], a_lo[2];
#pragma unroll
            for (int mt = 0; mt < 2; mt++) {
                const float* ap = sA + (wr * 32 + mt * 16) * 40 + k8 * 8;
                wmma::load_matrix_sync(a_hi[mt], ap, 40);
                wmma::load_matrix_sync(a_lo[mt], ap, 40);
#pragma unroll
                for (int e = 0; e < a_hi[mt].num_elements; e++) {
                    float v = a_hi[mt].x[e];
                    float h = wmma::__float_to_tf32(v);
                    a_hi[mt].x[e] = h;
                    a_lo[mt].x[e] = wmma::__float_to_tf32(v - h);
                }
            }
#pragma unroll
            for (int nt = 0; nt < 4; nt++) {
                wmma::fragment<wmma::matrix_b, 16, 16, 8, wmma::precision::tf32, wmma::row_major> b_hi, b_lo;
                const float* bp = sB + (k8 * 8) * 136 + wc * 64 + nt * 16;
                wmma::load_matrix_sync(b_hi, bp, 136);
                wmma::load_matrix_sync(b_lo, bp, 136);
#pragma unroll
                for (int e = 0; e < b_hi.num_elements; e++) {
                    float v = b_hi.x[e];
                    float h = wmma::__float_to_tf32(v);
                    b_hi.x[e] = h;
                    b_lo.x[e] = wmma::__float_to_tf32(v - h);
                }
#pragma unroll
                for (int mt = 0; mt < 2; mt++) {
                    wmma::mma_sync(acc[mt][nt], a_hi[mt], b_hi, acc[mt][nt]);  // hi*hi
                    wmma::mma_sync(acc[mt][nt], a_hi[mt], b_lo, acc[mt][nt]);  // hi*lo
                    wmma::mma_sync(acc[mt][nt], a_lo[mt], b_hi, acc[mt][nt]);  // lo*hi
                }
            }
        }
    }

    // epilogue: per-warp staging (16x64 = 4 KB each), dinv scale, vector store
    __syncthreads();                       // everyone done reading sA/sB
    float* stage = smem + warp * 1024;     // 8 warps x 1024 floats = 32 KB <= 9472
#pragma unroll
    for (int mt = 0; mt < 2; mt++) {
#pragma unroll
        for (int nt = 0; nt < 4; nt++)
            wmma::store_matrix_sync(stage + nt * 16, acc[mt][nt], 64, wmma::mem_row_major);
        __syncwarp();
#pragma unroll
        for (int i = 0; i < 8; i++) {
            int idx = lane + 32 * i;       // 256 float4s = 16 rows x 16 float4
            int r = idx >> 4, c4 = idx & 15;
            int row = rowBase + wr * 32 + mt * 16 + r;
            if (row < NN) {
                float s = g_dinv[row];
                float4 v = *(float4*)&stage[r * 64 + c4 * 4];
                v.x *= s; v.y *= s; v.z *= s; v.w *= s;
                *(float4*)&g_bufA[(size_t)row * F + wc * 64 + c4 * 4] = v;
            }
        }
        __syncwarp();
    }
}

// ---------------- aggregation: bufB[i] = relu(dinv[i]*(bufA[i] + sum bufA[nbr]) + b) ----------------
// one warp per node, float4 per lane (R3-exact: simple loop, MLP_p1 = 1)
__global__ void k_agg(const float* __restrict__ bias) {
    int w = (blockIdx.x * blockDim.x + threadIdx.x) >> 5;
    int lane = threadIdx.x & 31;
    if (w >= NN) return;
    const float4* g4 = (const float4*)g_bufA;
    float4 acc = g4[(size_t)w * 32 + lane];   // self loop term
    int s = g_rowptr[w], e = g_rowptr[w + 1];
    for (int p = s; p < e; p++) {
        int j = g_col[p];
        float4 v = g4[(size_t)j * 32 + lane];
        acc.x += v.x; acc.y += v.y; acc.z += v.z; acc.w += v.w;
    }
    float di = g_dinv[w];
    float4 b = ((const float4*)bias)[lane];
    float4 o;
    o.x = fmaxf(fmaf(acc.x, di, b.x), 0.f);
    o.y = fmaxf(fmaf(acc.y, di, b.y), 0.f);
    o.z = fmaxf(fmaf(acc.z, di, b.z), 0.f);
    o.w = fmaxf(fmaf(acc.w, di, b.w), 0.f);
    ((float4*)g_bufB)[(size_t)w * 32 + lane] = o;
}

// ---------------- fused heads (reads g_bufB) ----------------
__global__ void k_head(const float* __restrict__ Wp1, const float* __restrict__ bp1,
                       const float* __restrict__ Wp2, const float* __restrict__ bp2,
                       const float* __restrict__ Wt1, const float* __restrict__ bt1,
                       const float* __restrict__ Wt2, const float* __restrict__ bt2,
                       float* __restrict__ out) {
    __shared__ float sX[32 * F];    // 16 KB
    __shared__ float sWp[32 * F];   // 16 KB (K-quarter of Wp1)
    __shared__ float sWt[32 * 64];  // 8 KB  (K-quarter of Wt1)
    int tid = threadIdx.x;
    int rowBase = blockIdx.x * 32;
    {
        const float4* a = (const float4*)g_bufB;
#pragma unroll
        for (int i = 0; i < 4; i++) {
            int idx = tid + 256 * i;
            int r = rowBase + (idx >> 5);
            float4 v = make_float4(0.f, 0.f, 0.f, 0.f);
            if (r < NN) v = a[(size_t)r * 32 + (idx & 31)];
            ((float4*)sX)[idx] = v;
        }
    }
    int warp = tid >> 5, lane = tid & 31;
    float4 accp[4];
    float2 acct[4];
#pragma unroll
    for (int r = 0; r < 4; r++) {
        accp[r] = make_float4(0.f, 0.f, 0.f, 0.f);
        acct[r] = make_float2(0.f, 0.f);
    }

    for (int q = 0; q < 4; q++) {
        __syncthreads();
        {
            const float4* wp4 = (const float4*)(Wp1 + q * 32 * F);
#pragma unroll
            for (int i = 0; i < 4; i++) ((float4*)sWp)[tid + 256 * i] = wp4[tid + 256 * i];
            const float4* wt4 = (const float4*)(Wt1 + q * 32 * 64);
#pragma unroll
            for (int i = 0; i < 2; i++) ((float4*)sWt)[tid + 256 * i] = wt4[tid + 256 * i];
        }
        __syncthreads();
        const float* xr = sX + (warp * 4) * F + q * 32;
#pragma unroll 4
        for (int k = 0; k < 32; k++) {
            float4 wp = ((const float4*)(sWp + k * F))[lane];
            float2 wt = ((const float2*)(sWt + k * 64))[lane];
#pragma unroll
            for (int r = 0; r < 4; r++) {
                float xv = xr[r * F + k];
                accp[r].x = fmaf(xv, wp.x, accp[r].x);
                accp[r].y = fmaf(xv, wp.y, accp[r].y);
                accp[r].z = fmaf(xv, wp.z, accp[r].z);
                accp[r].w = fmaf(xv, wp.w, accp[r].w);
                acct[r].x = fmaf(xv, wt.x, acct[r].x);
                acct[r].y = fmaf(xv, wt.y, acct[r].y);
            }
        }
    }

    // epilogue: per-lane second-layer weights, warp reduce
    float4 bP = ((const float4*)bp1)[lane];
    float2 bT = ((const float2*)bt1)[lane];
    float wp2a[4], wp2b[4];
#pragma unroll
    for (int i = 0; i < 4; i++) {
        wp2a[i] = Wp2[(lane * 4 + i) * 2];
        wp2b[i] = Wp2[(lane * 4 + i) * 2 + 1];
    }
    float wt2_0 = Wt2[lane * 2], wt2_1 = Wt2[lane * 2 + 1];
    float bpos0 = bp2[0], bpos1 = bp2[1], btime = bt2[0];

#pragma unroll
    for (int r = 0; r < 4; r++) {
        int row = rowBase + warp * 4 + r;
        float p0 = fmaxf(accp[r].x + bP.x, 0.f);
        float p1 = fmaxf(accp[r].y + bP.y, 0.f);
        float p2 = fmaxf(accp[r].z + bP.z, 0.f);
        float p3 = fmaxf(accp[r].w + bP.w, 0.f);
        float t0 = fmaxf(acct[r].x + bT.x, 0.f);
        float t1 = fmaxf(acct[r].y + bT.y, 0.f);
        float px = p0 * wp2a[0] + p1 * wp2a[1] + p2 * wp2a[2] + p3 * wp2a[3];
        float py = p0 * wp2b[0] + p1 * wp2b[1] + p2 * wp2b[2] + p3 * wp2b[3];
        float tv = t0 * wt2_0 + t1 * wt2_1;
#pragma unroll
        for (int off = 16; off; off >>= 1) {
            px += __shfl_down_sync(0xffffffffu, px, off);
            py += __shfl_down_sync(0xffffffffu, py, off);
            tv += __shfl_down_sync(0xffffffffu, tv, off);
        }
        if (lane == 0 && row < NN) {
            out[(size_t)row * 3 + 0] = px + bpos0;
            out[(size_t)row * 3 + 1] = py + bpos1;
            out[(size_t)row * 3 + 2] = tv + btime;
        }
    }
}

// ---------------- launch ----------------
extern "C" void kernel_launch(void* const* d_in, const int* in_sizes, int n_in,
                              void* d_out, int out_size) {
    const float* x   = (const float*)d_in[0];
    const void*  ei  = d_in[1];
    const float* W1  = (const float*)d_in[2];  const float* b1  = (const float*)d_in[3];
    const float* W2  = (const float*)d_in[4];  const float* b2  = (const float*)d_in[5];
    const float* W3  = (const float*)d_in[6];  const float* b3  = (const float*)d_in[7];
    const float* Wp1 = (const float*)d_in[8];  const float* bp1 = (const float*)d_in[9];
    const float* Wp2 = (const float*)d_in[10]; const float* bp2 = (const float*)d_in[11];
    const float* Wt1 = (const float*)d_in[12]; const float* bt1 = (const float*)d_in[13];
    const float* Wt2 = (const float*)d_in[14]; const float* bt2 = (const float*)d_in[15];
    float* out = (float*)d_out;

    int nb256  = (NN + 255) / 256;
    int ebl    = (EE + 255) / 256;
    int nbScan = (NN + 1023) / 1024;

    k_detect<<<1, 1024>>>((const int*)ei);
    k_zero<<<nb256, 256>>>();
    k_hist<<<ebl, 256>>>(ei);
    k_dinv<<<nb256, 256>>>();
    k_scan1<<<nbScan, 1024>>>();
    k_scan2<<<1, 1>>>(nbScan);
    k_scan3<<<nb256, 256>>>();
    k_fill<<<ebl, 256>>>(ei);

    int gemmGrid = (NN + 127) / 128;   // 782
    int aggGrid  = (NN + 7) / 8;       // 1 warp per node
    int headGrid = (NN + 31) / 32;

    k_gemm<<<gemmGrid, 256>>>(x, W1);
    k_agg <<<aggGrid, 256>>>(b1);
    k_gemm<<<gemmGrid, 256>>>(nullptr, W2);
    k_agg <<<aggGrid, 256>>>(b2);
    k_gemm<<<gemmGrid, 256>>>(nullptr, W3);
    k_agg <<<aggGrid, 256>>>(b3);

    k_head<<<headGrid, 256>>>(Wp1, bp1, Wp2, bp2, Wt1, bt1, Wt2, bt2, out);
}

// round 12
// speedup vs baseline: 1.6338x; 1.2343x over previous
#include <cuda_runtime.h>
#include <cuda_fp16.h>

#define NN 100000
#define EE 1600000
#define F  128

// ---------------- device scratch (no allocations allowed) ----------------
__device__ __align__(16) __half g_bufH[(size_t)NN * F];  // 25.6 MB (gather buffer, fp16)
__device__ __align__(16) float  g_bufB[(size_t)NN * F];  // 51.2 MB (layer output, fp32)
__device__ float g_dinv[NN];
__device__ int   g_cnt[NN];
__device__ int   g_rowptr[NN + 1];
__device__ int   g_cursor[NN];
__device__ int   g_col[EE];
__device__ int   g_bsums[128];
__device__ int   g_is64;

// read edge index element (handles int32 or int64 storage)
__device__ __forceinline__ int ld_idx(const void* ei, size_t pos) {
    if (g_is64) return (int)((const long long*)ei)[pos];
    return ((const int*)ei)[pos];
}

// ---------------- dtype detect ----------------
__global__ void k_detect(const int* __restrict__ ei32) {
    __shared__ int nz;
    if (threadIdx.x == 0) nz = 0;
    __syncthreads();
    if (ei32[2 * threadIdx.x + 1] != 0) atomicOr(&nz, 1);
    __syncthreads();
    if (threadIdx.x == 0) g_is64 = (nz == 0) ? 1 : 0;
}

// ---------------- CSR build ----------------
__global__ void k_zero() {
    int i = blockIdx.x * blockDim.x + threadIdx.x;
    if (i < NN) g_cnt[i] = 0;
}

__global__ void k_hist(const void* __restrict__ ei) {
    int e = blockIdx.x * blockDim.x + threadIdx.x;
    if (e < EE) {
        int d = ld_idx(ei, (size_t)EE + e);
        atomicAdd(&g_cnt[d], 1);
    }
}

__global__ void k_dinv() {
    int i = blockIdx.x * blockDim.x + threadIdx.x;
    if (i < NN) g_dinv[i] = rsqrtf((float)(g_cnt[i] + 1));  // +1 self loop
}

__global__ void k_scan1() {
    __shared__ int s[1024];
    int t = threadIdx.x;
    int idx = blockIdx.x * 1024 + t;
    int v = (idx < NN) ? g_cnt[idx] : 0;
    s[t] = v;
    __syncthreads();
    for (int off = 1; off < 1024; off <<= 1) {
        int add = (t >= off) ? s[t - off] : 0;
        __syncthreads();
        s[t] += add;
        __syncthreads();
    }
    if (idx < NN) g_rowptr[idx] = s[t] - v;          // exclusive within block
    if (t == 1023) g_bsums[blockIdx.x] = s[t];       // block total
}

__global__ void k_scan2(int nb) {
    if (threadIdx.x == 0 && blockIdx.x == 0) {
        int run = 0;
        for (int b = 0; b < nb; b++) { int t = g_bsums[b]; g_bsums[b] = run; run += t; }
    }
}

__global__ void k_scan3() {
    int i = blockIdx.x * blockDim.x + threadIdx.x;
    if (i < NN) {
        int v = g_rowptr[i] + g_bsums[i >> 10];
        g_rowptr[i] = v;
        g_cursor[i] = v;
    }
    if (i == 0) g_rowptr[NN] = EE;
}

__global__ void k_fill(const void* __restrict__ ei) {
    int e = blockIdx.x * blockDim.x + threadIdx.x;
    if (e < EE) {
        int d = ld_idx(ei, (size_t)EE + e);
        int s = ld_idx(ei, (size_t)e);
        int p = atomicAdd(&g_cursor[d], 1);
        g_col[p] = s;
    }
}

// ---------------- GEMM (R3 FFMA path): g_bufH[row] = fp16( dinv[row] * (in[row] @ W) ) ----
// 256 threads/block, 32 rows/block (4 rows/warp). W held in smem in two
// 64-row halves (32 KB) + X tile (16 KB) = 48 KB static shared.
__global__ void k_gemm(const float* __restrict__ xext, const float* __restrict__ W) {
    __shared__ float sW[64 * F];   // 32 KB (one K-half of W)
    __shared__ float sX[32 * F];   // 16 KB
    const float* in = xext ? xext : g_bufB;
    int tid = threadIdx.x;
    int rowBase = blockIdx.x * 32;
    {
        const float4* a = (const float4*)in;
#pragma unroll
        for (int i = 0; i < 4; i++) {
            int idx = tid + 256 * i;
            int r = rowBase + (idx >> 5);
            float4 v = make_float4(0.f, 0.f, 0.f, 0.f);
            if (r < NN) v = a[(size_t)r * 32 + (idx & 31)];
            ((float4*)sX)[idx] = v;
        }
    }
    int warp = tid >> 5, lane = tid & 31;
    float4 acc[4];
#pragma unroll
    for (int r = 0; r < 4; r++) acc[r] = make_float4(0.f, 0.f, 0.f, 0.f);

    for (int h = 0; h < 2; h++) {
        __syncthreads();   // guards sX (h=0) and prior sW reads (h=1)
        {
            const float4* w4 = (const float4*)(W + h * 64 * F);
#pragma unroll
            for (int i = 0; i < 8; i++) ((float4*)sW)[tid + 256 * i] = w4[tid + 256 * i];
        }
        __syncthreads();
        const float* xr = sX + (warp * 4) * F + h * 64;
#pragma unroll 4
        for (int k = 0; k < 64; k++) {
            float4 wv = ((const float4*)(sW + k * F))[lane];
#pragma unroll
            for (int r = 0; r < 4; r++) {
                float xv = xr[r * F + k];
                acc[r].x = fmaf(xv, wv.x, acc[r].x);
                acc[r].y = fmaf(xv, wv.y, acc[r].y);
                acc[r].z = fmaf(xv, wv.z, acc[r].z);
                acc[r].w = fmaf(xv, wv.w, acc[r].w);
            }
        }
    }
#pragma unroll
    for (int r = 0; r < 4; r++) {
        int row = rowBase + warp * 4 + r;
        if (row < NN) {
            float s = g_dinv[row];
            float4 v = acc[r];
            __half2 h01 = __floats2half2_rn(v.x * s, v.y * s);
            __half2 h23 = __floats2half2_rn(v.z * s, v.w * s);
            uint2 u;
            u.x = *(unsigned*)&h01;
            u.y = *(unsigned*)&h23;
            ((uint2*)g_bufH)[(size_t)row * 32 + lane] = u;
        }
    }
}

// ---------------- aggregation: bufB[i] = relu(dinv[i]*(H[i] + sum H[nbr]) + b) ----------------
// one warp per node, 4 halfs (8B) per lane, fp32 accumulate (R3 loop shape: MLP_p1 = 1)
__global__ void k_agg(const float* __restrict__ bias) {
    int w = (blockIdx.x * blockDim.x + threadIdx.x) >> 5;
    int lane = threadIdx.x & 31;
    if (w >= NN) return;
    const uint2* g2 = (const uint2*)g_bufH;
    float4 acc;
    {
        uint2 u = g2[(size_t)w * 32 + lane];   // self loop term
        float2 f01 = __half22float2(*(__half2*)&u.x);
        float2 f23 = __half22float2(*(__half2*)&u.y);
        acc = make_float4(f01.x, f01.y, f23.x, f23.y);
    }
    int s = g_rowptr[w], e = g_rowptr[w + 1];
    for (int p = s; p < e; p++) {
        int j = g_col[p];
        uint2 u = g2[(size_t)j * 32 + lane];
        float2 f01 = __half22float2(*(__half2*)&u.x);
        float2 f23 = __half22float2(*(__half2*)&u.y);
        acc.x += f01.x; acc.y += f01.y; acc.z += f23.x; acc.w += f23.y;
    }
    float di = g_dinv[w];
    float4 b = ((const float4*)bias)[lane];
    float4 o;
    o.x = fmaxf(fmaf(acc.x, di, b.x), 0.f);
    o.y = fmaxf(fmaf(acc.y, di, b.y), 0.f);
    o.z = fmaxf(fmaf(acc.z, di, b.z), 0.f);
    o.w = fmaxf(fmaf(acc.w, di, b.w), 0.f);
    ((float4*)g_bufB)[(size_t)w * 32 + lane] = o;
}

// ---------------- fused heads (reads g_bufB) ----------------
// pos = relu(h@Wp1+bp1)@Wp2 + bp2 ; time = relu(h@Wt1+bt1)@Wt2 + bt2
__global__ void k_head(const float* __restrict__ Wp1, const float* __restrict__ bp1,
                       const float* __restrict__ Wp2, const float* __restrict__ bp2,
                       const float* __restrict__ Wt1, const float* __restrict__ bt1,
                       const float* __restrict__ Wt2, const float* __restrict__ bt2,
                       float* __restrict__ out) {
    __shared__ float sX[32 * F];    // 16 KB
    __shared__ float sWp[32 * F];   // 16 KB (K-quarter of Wp1)
    __shared__ float sWt[32 * 64];  // 8 KB  (K-quarter of Wt1)
    int tid = threadIdx.x;
    int rowBase = blockIdx.x * 32;
    {
        const float4* a = (const float4*)g_bufB;
#pragma unroll
        for (int i = 0; i < 4; i++) {
            int idx = tid + 256 * i;
            int r = rowBase + (idx >> 5);
            float4 v = make_float4(0.f, 0.f, 0.f, 0.f);
            if (r < NN) v = a[(size_t)r * 32 + (idx & 31)];
            ((float4*)sX)[idx] = v;
        }
    }
    int warp = tid >> 5, lane = tid & 31;
    float4 accp[4];
    float2 acct[4];
#pragma unroll
    for (int r = 0; r < 4; r++) {
        accp[r] = make_float4(0.f, 0.f, 0.f, 0.f);
        acct[r] = make_float2(0.f, 0.f);
    }

    for (int q = 0; q < 4; q++) {
        __syncthreads();
        {
            const float4* wp4 = (const float4*)(Wp1 + q * 32 * F);
#pragma unroll
            for (int i = 0; i < 4; i++) ((float4*)sWp)[tid + 256 * i] = wp4[tid + 256 * i];
            const float4* wt4 = (const float4*)(Wt1 + q * 32 * 64);
#pragma unroll
            for (int i = 0; i < 2; i++) ((float4*)sWt)[tid + 256 * i] = wt4[tid + 256 * i];
        }
        __syncthreads();
        const float* xr = sX + (warp * 4) * F + q * 32;
#pragma unroll 4
        for (int k = 0; k < 32; k++) {
            float4 wp = ((const float4*)(sWp + k * F))[lane];
            float2 wt = ((const float2*)(sWt + k * 64))[lane];
#pragma unroll
            for (int r = 0; r < 4; r++) {
                float xv = xr[r * F + k];
                accp[r].x = fmaf(xv, wp.x, accp[r].x);
                accp[r].y = fmaf(xv, wp.y, accp[r].y);
                accp[r].z = fmaf(xv, wp.z, accp[r].z);
                accp[r].w = fmaf(xv, wp.w, accp[r].w);
                acct[r].x = fmaf(xv, wt.x, acct[r].x);
                acct[r].y = fmaf(xv, wt.y, acct[r].y);
            }
        }
    }

    // epilogue: per-lane second-layer weights, warp reduce
    float4 bP = ((const float4*)bp1)[lane];
    float2 bT = ((const float2*)bt1)[lane];
    float wp2a[4], wp2b[4];
#pragma unroll
    for (int i = 0; i < 4; i++) {
        wp2a[i] = Wp2[(lane * 4 + i) * 2];
        wp2b[i] = Wp2[(lane * 4 + i) * 2 + 1];
    }
    float wt2_0 = Wt2[lane * 2], wt2_1 = Wt2[lane * 2 + 1];
    float bpos0 = bp2[0], bpos1 = bp2[1], btime = bt2[0];

#pragma unroll
    for (int r = 0; r < 4; r++) {
        int row = rowBase + warp * 4 + r;
        float p0 = fmaxf(accp[r].x + bP.x, 0.f);
        float p1 = fmaxf(accp[r].y + bP.y, 0.f);
        float p2 = fmaxf(accp[r].z + bP.z, 0.f);
        float p3 = fmaxf(accp[r].w + bP.w, 0.f);
        float t0 = fmaxf(acct[r].x + bT.x, 0.f);
        float t1 = fmaxf(acct[r].y + bT.y, 0.f);
        float px = p0 * wp2a[0] + p1 * wp2a[1] + p2 * wp2a[2] + p3 * wp2a[3];
        float py = p0 * wp2b[0] + p1 * wp2b[1] + p2 * wp2b[2] + p3 * wp2b[3];
        float tv = t0 * wt2_0 + t1 * wt2_1;
#pragma unroll
        for (int off = 16; off; off >>= 1) {
            px += __shfl_down_sync(0xffffffffu, px, off);
            py += __shfl_down_sync(0xffffffffu, py, off);
            tv += __shfl_down_sync(0xffffffffu, tv, off);
        }
        if (lane == 0 && row < NN) {
            out[(size_t)row * 3 + 0] = px + bpos0;
            out[(size_t)row * 3 + 1] = py + bpos1;
            out[(size_t)row * 3 + 2] = tv + btime;
        }
    }
}

// ---------------- launch ----------------
extern "C" void kernel_launch(void* const* d_in, const int* in_sizes, int n_in,
                              void* d_out, int out_size) {
    const float* x   = (const float*)d_in[0];
    const void*  ei  = d_in[1];
    const float* W1  = (const float*)d_in[2];  const float* b1  = (const float*)d_in[3];
    const float* W2  = (const float*)d_in[4];  const float* b2  = (const float*)d_in[5];
    const float* W3  = (const float*)d_in[6];  const float* b3  = (const float*)d_in[7];
    const float* Wp1 = (const float*)d_in[8];  const float* bp1 = (const float*)d_in[9];
    const float* Wp2 = (const float*)d_in[10]; const float* bp2 = (const float*)d_in[11];
    const float* Wt1 = (const float*)d_in[12]; const float* bt1 = (const float*)d_in[13];
    const float* Wt2 = (const float*)d_in[14]; const float* bt2 = (const float*)d_in[15];
    float* out = (float*)d_out;

    int nb256  = (NN + 255) / 256;
    int ebl    = (EE + 255) / 256;
    int nbScan = (NN + 1023) / 1024;

    k_detect<<<1, 1024>>>((const int*)ei);
    k_zero<<<nb256, 256>>>();
    k_hist<<<ebl, 256>>>(ei);
    k_dinv<<<nb256, 256>>>();
    k_scan1<<<nbScan, 1024>>>();
    k_scan2<<<1, 1>>>(nbScan);
    k_scan3<<<nb256, 256>>>();
    k_fill<<<ebl, 256>>>(ei);

    int gemmGrid = (NN + 31) / 32;
    int aggGrid  = (NN + 7) / 8;   // 8 warps per 256-thread block, 1 warp per node

    k_gemm<<<gemmGrid, 256>>>(x, W1);
    k_agg <<<aggGrid, 256>>>(b1);
    k_gemm<<<gemmGrid, 256>>>(nullptr, W2);
    k_agg <<<aggGrid, 256>>>(b2);
    k_gemm<<<gemmGrid, 256>>>(nullptr, W3);
    k_agg <<<aggGrid, 256>>>(b3);

    k_head<<<gemmGrid, 256>>>(Wp1, bp1, Wp2, bp2, Wt1, bt1, Wt2, bt2, out);
}

// round 13
// speedup vs baseline: 2.3899x; 1.4628x over previous
#include <cuda_runtime.h>
#include <cuda_fp16.h>
#include <mma.h>

using namespace nvcuda;

#define NN 100000
#define EE 1600000
#define F  128

// ---------------- device scratch (no allocations allowed) ----------------
__device__ __align__(16) __half g_bufH[(size_t)NN * F];  // 25.6 MB (gather buffer, fp16)
__device__ __align__(16) float  g_bufB[(size_t)NN * F];  // 51.2 MB (layer output, fp32)
__device__ float g_dinv[NN];
__device__ int   g_cnt[NN];
__device__ int   g_rowptr[NN + 1];
__device__ int   g_cursor[NN];
__device__ int   g_col[EE];
__device__ int   g_bsums[128];
__device__ int   g_is64;

// read edge index element (handles int32 or int64 storage)
__device__ __forceinline__ int ld_idx(const void* ei, size_t pos) {
    if (g_is64) return (int)((const long long*)ei)[pos];
    return ((const int*)ei)[pos];
}

// ---------------- dtype detect ----------------
__global__ void k_detect(const int* __restrict__ ei32) {
    __shared__ int nz;
    if (threadIdx.x == 0) nz = 0;
    __syncthreads();
    if (ei32[2 * threadIdx.x + 1] != 0) atomicOr(&nz, 1);
    __syncthreads();
    if (threadIdx.x == 0) g_is64 = (nz == 0) ? 1 : 0;
}

// ---------------- CSR build ----------------
__global__ void k_zero() {
    int i = blockIdx.x * blockDim.x + threadIdx.x;
    if (i < NN) g_cnt[i] = 0;
}

__global__ void k_hist(const void* __restrict__ ei) {
    int e = blockIdx.x * blockDim.x + threadIdx.x;
    if (e < EE) {
        int d = ld_idx(ei, (size_t)EE + e);
        atomicAdd(&g_cnt[d], 1);
    }
}

__global__ void k_dinv() {
    int i = blockIdx.x * blockDim.x + threadIdx.x;
    if (i < NN) g_dinv[i] = rsqrtf((float)(g_cnt[i] + 1));  // +1 self loop
}

__global__ void k_scan1() {
    __shared__ int s[1024];
    int t = threadIdx.x;
    int idx = blockIdx.x * 1024 + t;
    int v = (idx < NN) ? g_cnt[idx] : 0;
    s[t] = v;
    __syncthreads();
    for (int off = 1; off < 1024; off <<= 1) {
        int add = (t >= off) ? s[t - off] : 0;
        __syncthreads();
        s[t] += add;
        __syncthreads();
    }
    if (idx < NN) g_rowptr[idx] = s[t] - v;          // exclusive within block
    if (t == 1023) g_bsums[blockIdx.x] = s[t];       // block total
}

__global__ void k_scan2(int nb) {
    if (threadIdx.x == 0 && blockIdx.x == 0) {
        int run = 0;
        for (int b = 0; b < nb; b++) { int t = g_bsums[b]; g_bsums[b] = run; run += t; }
    }
}

__global__ void k_scan3() {
    int i = blockIdx.x * blockDim.x + threadIdx.x;
    if (i < NN) {
        int v = g_rowptr[i] + g_bsums[i >> 10];
        g_rowptr[i] = v;
        g_cursor[i] = v;
    }
    if (i == 0) g_rowptr[NN] = EE;
}

__global__ void k_fill(const void* __restrict__ ei) {
    int e = blockIdx.x * blockDim.x + threadIdx.x;
    if (e < EE) {
        int d = ld_idx(ei, (size_t)EE + e);
        int s = ld_idx(ei, (size_t)e);
        int p = atomicAdd(&g_cursor[d], 1);
        g_col[p] = s;
    }
}

// ---------------- GEMM (fp16 wmma, fp32 accumulate): ----------------
// g_bufH[row] = fp16( dinv[row] * (in[row] @ W) )
// Block: 256 threads = 8 warps, 128 rows x 128 cols.
// Warp (wr = w>>1 in 0..3, wc = w&1): rows wr*32..+32 (2 m16 tiles), cols wc*64..+64 (4 n16 tiles).
// K streamed in chunks of 32 (2 k16 steps). smem staged as fp16 with padded ldm
// (A: 40 halfs = 80 B, B: 136 halfs = 272 B — both 16 B multiples).
__global__ void k_gemm(const float* __restrict__ xext, const float* __restrict__ W) {
    __shared__ float smem[8192];                        // 32 KB; aliased
    __half* sA = reinterpret_cast<__half*>(smem);        // 128 x 40 halfs (10240 B)
    __half* sB = reinterpret_cast<__half*>(smem + 2560); // 32 x 136 halfs (8704 B)

    const float* in = xext ? xext : g_bufB;
    int tid  = threadIdx.x;
    int warp = tid >> 5, lane = tid & 31;
    int wr = warp >> 1;                   // 0..3
    int wc = warp & 1;                    // 0..1
    int rowBase = blockIdx.x * 128;

    wmma::fragment<wmma::accumulator, 16, 16, 16, float> acc[2][4];
#pragma unroll
    for (int mt = 0; mt < 2; mt++)
#pragma unroll
        for (int nt = 0; nt < 4; nt++) wmma::fill_fragment(acc[mt][nt], 0.0f);

    for (int kc = 0; kc < 4; kc++) {
        __syncthreads();
        // stage A chunk: 128 rows x 32 cols -> fp16 (2048 half2)
#pragma unroll
        for (int i = 0; i < 8; i++) {
            int idx = tid + 256 * i;             // 0..2047
            int r = idx >> 4, c2 = idx & 15;     // 16 half2 per row
            int row = rowBase + r;
            float2 v = make_float2(0.f, 0.f);
            if (row < NN) v = ((const float2*)in)[(size_t)row * 64 + kc * 16 + c2];
            *(__half2*)&sA[r * 40 + c2 * 2] = __floats2half2_rn(v.x, v.y);
        }
        // stage B chunk: 32 rows x 128 cols -> fp16 (2048 half2)
#pragma unroll
        for (int i = 0; i < 8; i++) {
            int idx = tid + 256 * i;             // 0..2047
            int k = idx >> 6, c2 = idx & 63;     // 64 half2 per row
            float2 v = ((const float2*)W)[(size_t)(kc * 32 + k) * 64 + c2];
            *(__half2*)&sB[k * 136 + c2 * 2] = __floats2half2_rn(v.x, v.y);
        }
        __syncthreads();

#pragma unroll
        for (int k16 = 0; k16 < 2; k16++) {
            wmma::fragment<wmma::matrix_a, 16, 16, 16, __half, wmma::row_major> a[2];
#pragma unroll
            for (int mt = 0; mt < 2; mt++)
                wmma::load_matrix_sync(a[mt], sA + (wr * 32 + mt * 16) * 40 + k16 * 16, 40);
#pragma unroll
            for (int nt = 0; nt < 4; nt++) {
                wmma::fragment<wmma::matrix_b, 16, 16, 16, __half, wmma::row_major> b;
                wmma::load_matrix_sync(b, sB + (k16 * 16) * 136 + wc * 64 + nt * 16, 136);
#pragma unroll
                for (int mt = 0; mt < 2; mt++)
                    wmma::mma_sync(acc[mt][nt], a[mt], b, acc[mt][nt]);
            }
        }
    }

    // epilogue: per-warp fp32 staging (16x64), dinv scale, convert to fp16, store
    __syncthreads();                       // all reads of sA/sB done
    float* stage = smem + warp * 1024;     // 8 warps x 1024 floats = 32 KB
#pragma unroll
    for (int mt = 0; mt < 2; mt++) {
#pragma unroll
        for (int nt = 0; nt < 4; nt++)
            wmma::store_matrix_sync(stage + nt * 16, acc[mt][nt], 64, wmma::mem_row_major);
        __syncwarp();
#pragma unroll
        for (int i = 0; i < 8; i++) {
            int idx = lane + 32 * i;       // 256 float4s = 16 rows x 16 float4
            int r = idx >> 4, c4 = idx & 15;
            int row = rowBase + wr * 32 + mt * 16 + r;
            if (row < NN) {
                float s = g_dinv[row];
                float4 v = *(float4*)&stage[r * 64 + c4 * 4];
                __half2 h01 = __floats2half2_rn(v.x * s, v.y * s);
                __half2 h23 = __floats2half2_rn(v.z * s, v.w * s);
                uint2 u;
                u.x = *(unsigned*)&h01;
                u.y = *(unsigned*)&h23;
                ((uint2*)g_bufH)[(size_t)row * 32 + (wc * 16 + c4)] = u;
            }
        }
        __syncwarp();
    }
}

// ---------------- aggregation: bufB[i] = relu(dinv[i]*(H[i] + sum H[nbr]) + b) ----------------
// one warp per node, 4 halfs (8B) per lane, fp32 accumulate (MLP_p1 = 1)
__global__ void k_agg(const float* __restrict__ bias) {
    int w = (blockIdx.x * blockDim.x + threadIdx.x) >> 5;
    int lane = threadIdx.x & 31;
    if (w >= NN) return;
    const uint2* g2 = (const uint2*)g_bufH;
    float4 acc;
    {
        uint2 u = g2[(size_t)w * 32 + lane];   // self loop term
        float2 f01 = __half22float2(*(__half2*)&u.x);
        float2 f23 = __half22float2(*(__half2*)&u.y);
        acc = make_float4(f01.x, f01.y, f23.x, f23.y);
    }
    int s = g_rowptr[w], e = g_rowptr[w + 1];
    for (int p = s; p < e; p++) {
        int j = g_col[p];
        uint2 u = g2[(size_t)j * 32 + lane];
        float2 f01 = __half22float2(*(__half2*)&u.x);
        float2 f23 = __half22float2(*(__half2*)&u.y);
        acc.x += f01.x; acc.y += f01.y; acc.z += f23.x; acc.w += f23.y;
    }
    float di = g_dinv[w];
    float4 b = ((const float4*)bias)[lane];
    float4 o;
    o.x = fmaxf(fmaf(acc.x, di, b.x), 0.f);
    o.y = fmaxf(fmaf(acc.y, di, b.y), 0.f);
    o.z = fmaxf(fmaf(acc.z, di, b.z), 0.f);
    o.w = fmaxf(fmaf(acc.w, di, b.w), 0.f);
    ((float4*)g_bufB)[(size_t)w * 32 + lane] = o;
}

// ---------------- fused heads (reads g_bufB), fp32 FFMA ----------------
__global__ void k_head(const float* __restrict__ Wp1, const float* __restrict__ bp1,
                       const float* __restrict__ Wp2, const float* __restrict__ bp2,
                       const float* __restrict__ Wt1, const float* __restrict__ bt1,
                       const float* __restrict__ Wt2, const float* __restrict__ bt2,
                       float* __restrict__ out) {
    __shared__ float sX[32 * F];    // 16 KB
    __shared__ float sWp[32 * F];   // 16 KB (K-quarter of Wp1)
    __shared__ float sWt[32 * 64];  // 8 KB  (K-quarter of Wt1)
    int tid = threadIdx.x;
    int rowBase = blockIdx.x * 32;
    {
        const float4* a = (const float4*)g_bufB;
#pragma unroll
        for (int i = 0; i < 4; i++) {
            int idx = tid + 256 * i;
            int r = rowBase + (idx >> 5);
            float4 v = make_float4(0.f, 0.f, 0.f, 0.f);
            if (r < NN) v = a[(size_t)r * 32 + (idx & 31)];
            ((float4*)sX)[idx] = v;
        }
    }
    int warp = tid >> 5, lane = tid & 31;
    float4 accp[4];
    float2 acct[4];
#pragma unroll
    for (int r = 0; r < 4; r++) {
        accp[r] = make_float4(0.f, 0.f, 0.f, 0.f);
        acct[r] = make_float2(0.f, 0.f);
    }

    for (int q = 0; q < 4; q++) {
        __syncthreads();
        {
            const float4* wp4 = (const float4*)(Wp1 + q * 32 * F);
#pragma unroll
            for (int i = 0; i < 4; i++) ((float4*)sWp)[tid + 256 * i] = wp4[tid + 256 * i];
            const float4* wt4 = (const float4*)(Wt1 + q * 32 * 64);
#pragma unroll
            for (int i = 0; i < 2; i++) ((float4*)sWt)[tid + 256 * i] = wt4[tid + 256 * i];
        }
        __syncthreads();
        const float* xr = sX + (warp * 4) * F + q * 32;
#pragma unroll 4
        for (int k = 0; k < 32; k++) {
            float4 wp = ((const float4*)(sWp + k * F))[lane];
            float2 wt = ((const float2*)(sWt + k * 64))[lane];
#pragma unroll
            for (int r = 0; r < 4; r++) {
                float xv = xr[r * F + k];
                accp[r].x = fmaf(xv, wp.x, accp[r].x);
                accp[r].y = fmaf(xv, wp.y, accp[r].y);
                accp[r].z = fmaf(xv, wp.z, accp[r].z);
                accp[r].w = fmaf(xv, wp.w, accp[r].w);
                acct[r].x = fmaf(xv, wt.x, acct[r].x);
                acct[r].y = fmaf(xv, wt.y, acct[r].y);
            }
        }
    }

    // epilogue: per-lane second-layer weights, warp reduce
    float4 bP = ((const float4*)bp1)[lane];
    float2 bT = ((const float2*)bt1)[lane];
    float wp2a[4], wp2b[4];
#pragma unroll
    for (int i = 0; i < 4; i++) {
        wp2a[i] = Wp2[(lane * 4 + i) * 2];
        wp2b[i] = Wp2[(lane * 4 + i) * 2 + 1];
    }
    float wt2_0 = Wt2[lane * 2], wt2_1 = Wt2[lane * 2 + 1];
    float bpos0 = bp2[0], bpos1 = bp2[1], btime = bt2[0];

#pragma unroll
    for (int r = 0; r < 4; r++) {
        int row = rowBase + warp * 4 + r;
        float p0 = fmaxf(accp[r].x + bP.x, 0.f);
        float p1 = fmaxf(accp[r].y + bP.y, 0.f);
        float p2 = fmaxf(accp[r].z + bP.z, 0.f);
        float p3 = fmaxf(accp[r].w + bP.w, 0.f);
        float t0 = fmaxf(acct[r].x + bT.x, 0.f);
        float t1 = fmaxf(acct[r].y + bT.y, 0.f);
        float px = p0 * wp2a[0] + p1 * wp2a[1] + p2 * wp2a[2] + p3 * wp2a[3];
        float py = p0 * wp2b[0] + p1 * wp2b[1] + p2 * wp2b[2] + p3 * wp2b[3];
        float tv = t0 * wt2_0 + t1 * wt2_1;
#pragma unroll
        for (int off = 16; off; off >>= 1) {
            px += __shfl_down_sync(0xffffffffu, px, off);
            py += __shfl_down_sync(0xffffffffu, py, off);
            tv += __shfl_down_sync(0xffffffffu, tv, off);
        }
        if (lane == 0 && row < NN) {
            out[(size_t)row * 3 + 0] = px + bpos0;
            out[(size_t)row * 3 + 1] = py + bpos1;
            out[(size_t)row * 3 + 2] = tv + btime;
        }
    }
}

// ---------------- launch ----------------
extern "C" void kernel_launch(void* const* d_in, const int* in_sizes, int n_in,
                              void* d_out, int out_size) {
    const float* x   = (const float*)d_in[0];
    const void*  ei  = d_in[1];
    const float* W1  = (const float*)d_in[2];  const float* b1  = (const float*)d_in[3];
    const float* W2  = (const float*)d_in[4];  const float* b2  = (const float*)d_in[5];
    const float* W3  = (const float*)d_in[6];  const float* b3  = (const float*)d_in[7];
    const float* Wp1 = (const float*)d_in[8];  const float* bp1 = (const float*)d_in[9];
    const float* Wp2 = (const float*)d_in[10]; const float* bp2 = (const float*)d_in[11];
    const float* Wt1 = (const float*)d_in[12]; const float* bt1 = (const float*)d_in[13];
    const float* Wt2 = (const float*)d_in[14]; const float* bt2 = (const float*)d_in[15];
    float* out = (float*)d_out;

    int nb256  = (NN + 255) / 256;
    int ebl    = (EE + 255) / 256;
    int nbScan = (NN + 1023) / 1024;

    k_detect<<<1, 1024>>>((const int*)ei);
    k_zero<<<nb256, 256>>>();
    k_hist<<<ebl, 256>>>(ei);
    k_dinv<<<nb256, 256>>>();
    k_scan1<<<nbScan, 1024>>>();
    k_scan2<<<1, 1>>>(nbScan);
    k_scan3<<<nb256, 256>>>();
    k_fill<<<ebl, 256>>>(ei);

    int gemmGrid = (NN + 127) / 128;   // 782
    int aggGrid  = (NN + 7) / 8;       // 1 warp per node
    int headGrid = (NN + 31) / 32;

    k_gemm<<<gemmGrid, 256>>>(x, W1);
    k_agg <<<aggGrid, 256>>>(b1);
    k_gemm<<<gemmGrid, 256>>>(nullptr, W2);
    k_agg <<<aggGrid, 256>>>(b2);
    k_gemm<<<gemmGrid, 256>>>(nullptr, W3);
    k_agg <<<aggGrid, 256>>>(b3);

    k_head<<<headGrid, 256>>>(Wp1, bp1, Wp2, bp2, Wt1, bt1, Wt2, bt2, out);
}

// round 14
// speedup vs baseline: 2.7259x; 1.1406x over previous
#include <cuda_runtime.h>
#include <cuda_fp16.h>
#include <mma.h>

using namespace nvcuda;

#define NN 100000
#define EE 1600000
#define F  128

// ---------------- device scratch (no allocations allowed) ----------------
__device__ __align__(16) __half g_bufH[(size_t)NN * F];  // 25.6 MB (gather buffer, fp16)
__device__ __align__(16) float  g_bufB[(size_t)NN * F];  // 51.2 MB (layer output, fp32)
__device__ float g_dinv[NN];
__device__ int   g_cnt[NN];
__device__ int   g_rowptr[NN + 1];
__device__ int   g_cursor[NN];
__device__ int   g_col[EE];
__device__ int   g_bsums[128];
__device__ int   g_is64;

// read edge index element (handles int32 or int64 storage)
__device__ __forceinline__ int ld_idx(const void* ei, size_t pos) {
    if (g_is64) return (int)((const long long*)ei)[pos];
    return ((const int*)ei)[pos];
}

// ---------------- dtype detect ----------------
__global__ void k_detect(const int* __restrict__ ei32) {
    __shared__ int nz;
    if (threadIdx.x == 0) nz = 0;
    __syncthreads();
    if (ei32[2 * threadIdx.x + 1] != 0) atomicOr(&nz, 1);
    __syncthreads();
    if (threadIdx.x == 0) g_is64 = (nz == 0) ? 1 : 0;
}

// ---------------- CSR build ----------------
__global__ void k_zero() {
    int i = blockIdx.x * blockDim.x + threadIdx.x;
    if (i < NN) g_cnt[i] = 0;
}

__global__ void k_hist(const void* __restrict__ ei) {
    int e = blockIdx.x * blockDim.x + threadIdx.x;
    if (e < EE) {
        int d = ld_idx(ei, (size_t)EE + e);
        atomicAdd(&g_cnt[d], 1);
    }
}

__global__ void k_dinv() {
    int i = blockIdx.x * blockDim.x + threadIdx.x;
    if (i < NN) g_dinv[i] = rsqrtf((float)(g_cnt[i] + 1));  // +1 self loop
}

__global__ void k_scan1() {
    __shared__ int s[1024];
    int t = threadIdx.x;
    int idx = blockIdx.x * 1024 + t;
    int v = (idx < NN) ? g_cnt[idx] : 0;
    s[t] = v;
    __syncthreads();
    for (int off = 1; off < 1024; off <<= 1) {
        int add = (t >= off) ? s[t - off] : 0;
        __syncthreads();
        s[t] += add;
        __syncthreads();
    }
    if (idx < NN) g_rowptr[idx] = s[t] - v;          // exclusive within block
    if (t == 1023) g_bsums[blockIdx.x] = s[t];       // block total
}

__global__ void k_scan2(int nb) {
    if (threadIdx.x == 0 && blockIdx.x == 0) {
        int run = 0;
        for (int b = 0; b < nb; b++) { int t = g_bsums[b]; g_bsums[b] = run; run += t; }
    }
}

__global__ void k_scan3() {
    int i = blockIdx.x * blockDim.x + threadIdx.x;
    if (i < NN) {
        int v = g_rowptr[i] + g_bsums[i >> 10];
        g_rowptr[i] = v;
        g_cursor[i] = v;
    }
    if (i == 0) g_rowptr[NN] = EE;
}

__global__ void k_fill(const void* __restrict__ ei) {
    int e = blockIdx.x * blockDim.x + threadIdx.x;
    if (e < EE) {
        int d = ld_idx(ei, (size_t)EE + e);
        int s = ld_idx(ei, (size_t)e);
        int p = atomicAdd(&g_cursor[d], 1);
        g_col[p] = s;
    }
}

// ---------------- GEMM (fp16 wmma, fp32 accumulate): ----------------
// g_bufH[row] = fp16( dinv[row] * (in[row] @ W) )
__global__ void k_gemm(const float* __restrict__ xext, const float* __restrict__ W) {
    __shared__ float smem[8192];                        // 32 KB; aliased
    __half* sA = reinterpret_cast<__half*>(smem);        // 128 x 40 halfs (10240 B)
    __half* sB = reinterpret_cast<__half*>(smem + 2560); // 32 x 136 halfs (8704 B)

    const float* in = xext ? xext : g_bufB;
    int tid  = threadIdx.x;
    int warp = tid >> 5, lane = tid & 31;
    int wr = warp >> 1;                   // 0..3
    int wc = warp & 1;                    // 0..1
    int rowBase = blockIdx.x * 128;

    wmma::fragment<wmma::accumulator, 16, 16, 16, float> acc[2][4];
#pragma unroll
    for (int mt = 0; mt < 2; mt++)
#pragma unroll
        for (int nt = 0; nt < 4; nt++) wmma::fill_fragment(acc[mt][nt], 0.0f);

    for (int kc = 0; kc < 4; kc++) {
        __syncthreads();
#pragma unroll
        for (int i = 0; i < 8; i++) {
            int idx = tid + 256 * i;             // 0..2047
            int r = idx >> 4, c2 = idx & 15;
            int row = rowBase + r;
            float2 v = make_float2(0.f, 0.f);
            if (row < NN) v = ((const float2*)in)[(size_t)row * 64 + kc * 16 + c2];
            *(__half2*)&sA[r * 40 + c2 * 2] = __floats2half2_rn(v.x, v.y);
        }
#pragma unroll
        for (int i = 0; i < 8; i++) {
            int idx = tid + 256 * i;             // 0..2047
            int k = idx >> 6, c2 = idx & 63;
            float2 v = ((const float2*)W)[(size_t)(kc * 32 + k) * 64 + c2];
            *(__half2*)&sB[k * 136 + c2 * 2] = __floats2half2_rn(v.x, v.y);
        }
        __syncthreads();

#pragma unroll
        for (int k16 = 0; k16 < 2; k16++) {
            wmma::fragment<wmma::matrix_a, 16, 16, 16, __half, wmma::row_major> a[2];
#pragma unroll
            for (int mt = 0; mt < 2; mt++)
                wmma::load_matrix_sync(a[mt], sA + (wr * 32 + mt * 16) * 40 + k16 * 16, 40);
#pragma unroll
            for (int nt = 0; nt < 4; nt++) {
                wmma::fragment<wmma::matrix_b, 16, 16, 16, __half, wmma::row_major> b;
                wmma::load_matrix_sync(b, sB + (k16 * 16) * 136 + wc * 64 + nt * 16, 136);
#pragma unroll
                for (int mt = 0; mt < 2; mt++)
                    wmma::mma_sync(acc[mt][nt], a[mt], b, acc[mt][nt]);
            }
        }
    }

    __syncthreads();
    float* stage = smem + warp * 1024;
#pragma unroll
    for (int mt = 0; mt < 2; mt++) {
#pragma unroll
        for (int nt = 0; nt < 4; nt++)
            wmma::store_matrix_sync(stage + nt * 16, acc[mt][nt], 64, wmma::mem_row_major);
        __syncwarp();
#pragma unroll
        for (int i = 0; i < 8; i++) {
            int idx = lane + 32 * i;
            int r = idx >> 4, c4 = idx & 15;
            int row = rowBase + wr * 32 + mt * 16 + r;
            if (row < NN) {
                float s = g_dinv[row];
                float4 v = *(float4*)&stage[r * 64 + c4 * 4];
                __half2 h01 = __floats2half2_rn(v.x * s, v.y * s);
                __half2 h23 = __floats2half2_rn(v.z * s, v.w * s);
                uint2 u;
                u.x = *(unsigned*)&h01;
                u.y = *(unsigned*)&h23;
                ((uint2*)g_bufH)[(size_t)row * 32 + (wc * 16 + c4)] = u;
            }
        }
        __syncwarp();
    }
}

// ---------------- aggregation: bufB[i] = relu(dinv[i]*(H[i] + sum H[nbr]) + b) ----------------
__global__ void k_agg(const float* __restrict__ bias) {
    int w = (blockIdx.x * blockDim.x + threadIdx.x) >> 5;
    int lane = threadIdx.x & 31;
    if (w >= NN) return;
    const uint2* g2 = (const uint2*)g_bufH;
    float4 acc;
    {
        uint2 u = g2[(size_t)w * 32 + lane];   // self loop term
        float2 f01 = __half22float2(*(__half2*)&u.x);
        float2 f23 = __half22float2(*(__half2*)&u.y);
        acc = make_float4(f01.x, f01.y, f23.x, f23.y);
    }
    int s = g_rowptr[w], e = g_rowptr[w + 1];
    for (int p = s; p < e; p++) {
        int j = g_col[p];
        uint2 u = g2[(size_t)j * 32 + lane];
        float2 f01 = __half22float2(*(__half2*)&u.x);
        float2 f23 = __half22float2(*(__half2*)&u.y);
        acc.x += f01.x; acc.y += f01.y; acc.z += f23.x; acc.w += f23.y;
    }
    float di = g_dinv[w];
    float4 b = ((const float4*)bias)[lane];
    float4 o;
    o.x = fmaxf(fmaf(acc.x, di, b.x), 0.f);
    o.y = fmaxf(fmaf(acc.y, di, b.y), 0.f);
    o.z = fmaxf(fmaf(acc.z, di, b.z), 0.f);
    o.w = fmaxf(fmaf(acc.w, di, b.w), 0.f);
    ((float4*)g_bufB)[(size_t)w * 32 + lane] = o;
}

// ---------------- fused heads (fp16 wmma first layer, fp32 second layer) ----------------
// H1 = h @ [Wp1 | Wt1]  (192 cols, fp16 HMMA, fp32 acc)
// pos = relu(H1[:,0:128]+bp1) @ Wp2 + bp2 ; time = relu(H1[:,128:192]+bt1) @ Wt2 + bt2
// Block: 256 threads = 8 warps, 128 rows. Warp w: rows w*16..+16, all 12 n16-tiles.
// smem: sA 128x40 halfs (10240 B) + sB 32x200 halfs (12800 B) in loop;
// epilogue: 4 warps x (16x192 fp32 = 12288 B) = 48 KB, two batches.
__global__ void k_head(const float* __restrict__ Wp1, const float* __restrict__ bp1,
                       const float* __restrict__ Wp2, const float* __restrict__ bp2,
                       const float* __restrict__ Wt1, const float* __restrict__ bt1,
                       const float* __restrict__ Wt2, const float* __restrict__ bt2,
                       float* __restrict__ out) {
    __shared__ __align__(16) char smemraw[49152];      // 48 KB
    __half* sA = (__half*)smemraw;                     // 128 x 40 halfs
    __half* sB = (__half*)(smemraw + 10240);           // 32 x 200 halfs (192 used)
    float*  stageF = (float*)smemraw;                  // epilogue: 4 x 16x192 fp32

    int tid  = threadIdx.x;
    int warp = tid >> 5, lane = tid & 31;
    int rowBase = blockIdx.x * 128;

    wmma::fragment<wmma::accumulator, 16, 16, 16, float> acc[12];
#pragma unroll
    for (int nt = 0; nt < 12; nt++) wmma::fill_fragment(acc[nt], 0.0f);

    for (int kc = 0; kc < 4; kc++) {
        __syncthreads();
        // stage A chunk: 128 rows x 32 cols of h (fp32 -> fp16)
#pragma unroll
        for (int i = 0; i < 8; i++) {
            int idx = tid + 256 * i;             // 0..2047 half2
            int r = idx >> 4, c2 = idx & 15;
            int row = rowBase + r;
            float2 v = make_float2(0.f, 0.f);
            if (row < NN) v = ((const float2*)g_bufB)[(size_t)row * 64 + kc * 16 + c2];
            *(__half2*)&sA[r * 40 + c2 * 2] = __floats2half2_rn(v.x, v.y);
        }
        // stage B chunk: 32 rows x 192 cols = [Wp1 chunk | Wt1 chunk]
#pragma unroll
        for (int i = 0; i < 12; i++) {
            int idx = tid + 256 * i;             // 0..3071 half2
            int k = idx / 96, c2 = idx % 96;     // c2 in half2 units, col = c2*2
            int kg = kc * 32 + k;
            float2 v;
            if (c2 < 64) v = ((const float2*)Wp1)[(size_t)kg * 64 + c2];
            else         v = ((const float2*)Wt1)[(size_t)kg * 32 + (c2 - 64)];
            *(__half2*)&sB[k * 200 + c2 * 2] = __floats2half2_rn(v.x, v.y);
        }
        __syncthreads();

#pragma unroll
        for (int k16 = 0; k16 < 2; k16++) {
            wmma::fragment<wmma::matrix_a, 16, 16, 16, __half, wmma::row_major> a;
            wmma::load_matrix_sync(a, sA + (warp * 16) * 40 + k16 * 16, 40);
#pragma unroll
            for (int nt = 0; nt < 12; nt++) {
                wmma::fragment<wmma::matrix_b, 16, 16, 16, __half, wmma::row_major> b;
                wmma::load_matrix_sync(b, sB + (k16 * 16) * 200 + nt * 16, 200);
                wmma::mma_sync(acc[nt], a, b, acc[nt]);
            }
        }
    }

    // per-lane second-layer constants
    float4 bP = ((const float4*)bp1)[lane];
    float2 bT = ((const float2*)bt1)[lane];
    float wp2a[4], wp2b[4];
#pragma unroll
    for (int i = 0; i < 4; i++) {
        wp2a[i] = Wp2[(lane * 4 + i) * 2];
        wp2b[i] = Wp2[(lane * 4 + i) * 2 + 1];
    }
    float wt2_0 = Wt2[lane * 2], wt2_1 = Wt2[lane * 2 + 1];
    float bpos0 = bp2[0], bpos1 = bp2[1], btime = bt2[0];

    __syncthreads();   // all mainloop reads of sA/sB complete before staging overwrite
    for (int batch = 0; batch < 2; batch++) {
        bool mine = (warp >> 2) == batch;
        if (mine) {
            float* st = stageF + (warp & 3) * 3072;   // 16 x 192
#pragma unroll
            for (int nt = 0; nt < 12; nt++)
                wmma::store_matrix_sync(st + nt * 16, acc[nt], 192, wmma::mem_row_major);
            __syncwarp();
#pragma unroll 2
            for (int r = 0; r < 16; r++) {
                int row = rowBase + warp * 16 + r;
                float4 hv = *(float4*)&st[r * 192 + lane * 4];
                float2 tvv = *(float2*)&st[r * 192 + 128 + lane * 2];
                float p0 = fmaxf(hv.x + bP.x, 0.f);
                float p1 = fmaxf(hv.y + bP.y, 0.f);
                float p2 = fmaxf(hv.z + bP.z, 0.f);
                float p3 = fmaxf(hv.w + bP.w, 0.f);
                float t0 = fmaxf(tvv.x + bT.x, 0.f);
                float t1 = fmaxf(tvv.y + bT.y, 0.f);
                float px = p0 * wp2a[0] + p1 * wp2a[1] + p2 * wp2a[2] + p3 * wp2a[3];
                float py = p0 * wp2b[0] + p1 * wp2b[1] + p2 * wp2b[2] + p3 * wp2b[3];
                float tv = t0 * wt2_0 + t1 * wt2_1;
#pragma unroll
                for (int off = 16; off; off >>= 1) {
                    px += __shfl_down_sync(0xffffffffu, px, off);
                    py += __shfl_down_sync(0xffffffffu, py, off);
                    tv += __shfl_down_sync(0xffffffffu, tv, off);
                }
                if (lane == 0 && row < NN) {
                    out[(size_t)row * 3 + 0] = px + bpos0;
                    out[(size_t)row * 3 + 1] = py + bpos1;
                    out[(size_t)row * 3 + 2] = tv + btime;
                }
            }
        }
        __syncthreads();
    }
}

// ---------------- launch ----------------
extern "C" void kernel_launch(void* const* d_in, const int* in_sizes, int n_in,
                              void* d_out, int out_size) {
    const float* x   = (const float*)d_in[0];
    const void*  ei  = d_in[1];
    const float* W1  = (const float*)d_in[2];  const float* b1  = (const float*)d_in[3];
    const float* W2  = (const float*)d_in[4];  const float* b2  = (const float*)d_in[5];
    const float* W3  = (const float*)d_in[6];  const float* b3  = (const float*)d_in[7];
    const float* Wp1 = (const float*)d_in[8];  const float* bp1 = (const float*)d_in[9];
    const float* Wp2 = (const float*)d_in[10]; const float* bp2 = (const float*)d_in[11];
    const float* Wt1 = (const float*)d_in[12]; const float* bt1 = (const float*)d_in[13];
    const float* Wt2 = (const float*)d_in[14]; const float* bt2 = (const float*)d_in[15];
    float* out = (float*)d_out;

    int nb256  = (NN + 255) / 256;
    int ebl    = (EE + 255) / 256;
    int nbScan = (NN + 1023) / 1024;

    k_detect<<<1, 1024>>>((const int*)ei);
    k_zero<<<nb256, 256>>>();
    k_hist<<<ebl, 256>>>(ei);
    k_dinv<<<nb256, 256>>>();
    k_scan1<<<nbScan, 1024>>>();
    k_scan2<<<1, 1>>>(nbScan);
    k_scan3<<<nb256, 256>>>();
    k_fill<<<ebl, 256>>>(ei);

    int gemmGrid = (NN + 127) / 128;   // 782
    int aggGrid  = (NN + 7) / 8;       // 1 warp per node
    int headGrid = (NN + 127) / 128;   // 782

    k_gemm<<<gemmGrid, 256>>>(x, W1);
    k_agg <<<aggGrid, 256>>>(b1);
    k_gemm<<<gemmGrid, 256>>>(nullptr, W2);
    k_agg <<<aggGrid, 256>>>(b2);
    k_gemm<<<gemmGrid, 256>>>(nullptr, W3);
    k_agg <<<aggGrid, 256>>>(b3);

    k_head<<<headGrid, 256>>>(Wp1, bp1, Wp2, bp2, Wt1, bt1, Wt2, bt2, out);
}

// round 15
// speedup vs baseline: 2.9044x; 1.0655x over previous
#include <cuda_runtime.h>
#include <cuda_fp16.h>
#include <mma.h>

using namespace nvcuda;

#define NN 100000
#define EE 1600000
#define F  128

// ---------------- device scratch (no allocations allowed) ----------------
__device__ __align__(16) __half g_bufH[(size_t)NN * F];   // 25.6 MB (gather buffer: dinv*(XW), fp16)
__device__ __align__(16) __half g_bufB16[(size_t)NN * F]; // 25.6 MB (layer output h, fp16)
__device__ float g_dinv[NN];
__device__ int   g_cnt[NN];
__device__ int   g_rowptr[NN + 1];
__device__ int   g_cursor[NN];
__device__ int   g_col[EE];
__device__ int   g_bsums[128];
__device__ int   g_is64;

// read edge index element (handles int32 or int64 storage)
__device__ __forceinline__ int ld_idx(const void* ei, size_t pos) {
    if (g_is64) return (int)((const long long*)ei)[pos];
    return ((const int*)ei)[pos];
}

// ---------------- zero + dtype detect (fused) ----------------
// All blocks zero g_cnt; block 0 additionally samples edge words for dtype.
__global__ void k_zero_detect(const int* __restrict__ ei32) {
    int i = blockIdx.x * blockDim.x + threadIdx.x;
    if (i < NN) g_cnt[i] = 0;
    if (blockIdx.x == 0) {
        __shared__ int nz;
        if (threadIdx.x == 0) nz = 0;
        __syncthreads();
        // int64 edge values < 2^31 -> every odd 32-bit word is 0.
        // int32 -> odd words are src[1],src[3],... (random in [0,1e5)), ~never all zero.
        if (ei32[2 * threadIdx.x + 1] != 0) atomicOr(&nz, 1);
        __syncthreads();
        if (threadIdx.x == 0) g_is64 = (nz == 0) ? 1 : 0;
    }
}

// ---------------- CSR build ----------------
__global__ void k_hist(const void* __restrict__ ei) {
    int e = blockIdx.x * blockDim.x + threadIdx.x;
    if (e < EE) {
        int d = ld_idx(ei, (size_t)EE + e);
        atomicAdd(&g_cnt[d], 1);
    }
}

// scan1 also computes dinv (fused former k_dinv)
__global__ void k_scan1() {
    __shared__ int s[1024];
    int t = threadIdx.x;
    int idx = blockIdx.x * 1024 + t;
    int v = (idx < NN) ? g_cnt[idx] : 0;
    if (idx < NN) g_dinv[idx] = rsqrtf((float)(v + 1));  // +1 self loop
    s[t] = v;
    __syncthreads();
    for (int off = 1; off < 1024; off <<= 1) {
        int add = (t >= off) ? s[t - off] : 0;
        __syncthreads();
        s[t] += add;
        __syncthreads();
    }
    if (idx < NN) g_rowptr[idx] = s[t] - v;          // exclusive within block
    if (t == 1023) g_bsums[blockIdx.x] = s[t];       // block total
}

__global__ void k_scan2(int nb) {
    if (threadIdx.x == 0 && blockIdx.x == 0) {
        int run = 0;
        for (int b = 0; b < nb; b++) { int t = g_bsums[b]; g_bsums[b] = run; run += t; }
    }
}

__global__ void k_scan3() {
    int i = blockIdx.x * blockDim.x + threadIdx.x;
    if (i < NN) {
        int v = g_rowptr[i] + g_bsums[i >> 10];
        g_rowptr[i] = v;
        g_cursor[i] = v;
    }
    if (i == 0) g_rowptr[NN] = EE;
}

__global__ void k_fill(const void* __restrict__ ei) {
    int e = blockIdx.x * blockDim.x + threadIdx.x;
    if (e < EE) {
        int d = ld_idx(ei, (size_t)EE + e);
        int s = ld_idx(ei, (size_t)e);
        int p = atomicAdd(&g_cursor[d], 1);
        g_col[p] = s;
    }
}

// ---------------- GEMM (fp16 wmma, fp32 accumulate): ----------------
// g_bufH[row] = fp16( dinv[row] * (in[row] @ W) )
// Layer 1: in = xext (fp32, converted in staging). Layers 2/3: in = g_bufB16 (fp16, raw copy).
__global__ void k_gemm(const float* __restrict__ xext, const float* __restrict__ W) {
    __shared__ float smem[8192];                        // 32 KB; aliased
    __half* sA = reinterpret_cast<__half*>(smem);        // 128 x 40 halfs (10240 B)
    __half* sB = reinterpret_cast<__half*>(smem + 2560); // 32 x 136 halfs (8704 B)

    int tid  = threadIdx.x;
    int warp = tid >> 5, lane = tid & 31;
    int wr = warp >> 1;                   // 0..3
    int wc = warp & 1;                    // 0..1
    int rowBase = blockIdx.x * 128;

    wmma::fragment<wmma::accumulator, 16, 16, 16, float> acc[2][4];
#pragma unroll
    for (int mt = 0; mt < 2; mt++)
#pragma unroll
        for (int nt = 0; nt < 4; nt++) wmma::fill_fragment(acc[mt][nt], 0.0f);

    for (int kc = 0; kc < 4; kc++) {
        __syncthreads();
        // stage A chunk: 128 rows x 32 cols
        if (xext) {
#pragma unroll
            for (int i = 0; i < 8; i++) {
                int idx = tid + 256 * i;             // 0..2047 half2
                int r = idx >> 4, c2 = idx & 15;
                int row = rowBase + r;
                float2 v = make_float2(0.f, 0.f);
                if (row < NN) v = ((const float2*)xext)[(size_t)row * 64 + kc * 16 + c2];
                *(__half2*)&sA[r * 40 + c2 * 2] = __floats2half2_rn(v.x, v.y);
            }
        } else {
#pragma unroll
            for (int i = 0; i < 8; i++) {
                int idx = tid + 256 * i;             // 0..2047 half2
                int r = idx >> 4, c2 = idx & 15;
                int row = rowBase + r;
                unsigned u = 0;
                if (row < NN) u = ((const unsigned*)g_bufB16)[(size_t)row * 64 + kc * 16 + c2];
                *(unsigned*)&sA[r * 40 + c2 * 2] = u;
            }
        }
        // stage B chunk: 32 rows x 128 cols (fp32 -> fp16)
#pragma unroll
        for (int i = 0; i < 8; i++) {
            int idx = tid + 256 * i;             // 0..2047
            int k = idx >> 6, c2 = idx & 63;
            float2 v = ((const float2*)W)[(size_t)(kc * 32 + k) * 64 + c2];
            *(__half2*)&sB[k * 136 + c2 * 2] = __floats2half2_rn(v.x, v.y);
        }
        __syncthreads();

#pragma unroll
        for (int k16 = 0; k16 < 2; k16++) {
            wmma::fragment<wmma::matrix_a, 16, 16, 16, __half, wmma::row_major> a[2];
#pragma unroll
            for (int mt = 0; mt < 2; mt++)
                wmma::load_matrix_sync(a[mt], sA + (wr * 32 + mt * 16) * 40 + k16 * 16, 40);
#pragma unroll
            for (int nt = 0; nt < 4; nt++) {
                wmma::fragment<wmma::matrix_b, 16, 16, 16, __half, wmma::row_major> b;
                wmma::load_matrix_sync(b, sB + (k16 * 16) * 136 + wc * 64 + nt * 16, 136);
#pragma unroll
                for (int mt = 0; mt < 2; mt++)
                    wmma::mma_sync(acc[mt][nt], a[mt], b, acc[mt][nt]);
            }
        }
    }

    __syncthreads();
    float* stage = smem + warp * 1024;
#pragma unroll
    for (int mt = 0; mt < 2; mt++) {
#pragma unroll
        for (int nt = 0; nt < 4; nt++)
            wmma::store_matrix_sync(stage + nt * 16, acc[mt][nt], 64, wmma::mem_row_major);
        __syncwarp();
#pragma unroll
        for (int i = 0; i < 8; i++) {
            int idx = lane + 32 * i;
            int r = idx >> 4, c4 = idx & 15;
            int row = rowBase + wr * 32 + mt * 16 + r;
            if (row < NN) {
                float s = g_dinv[row];
                float4 v = *(float4*)&stage[r * 64 + c4 * 4];
                __half2 h01 = __floats2half2_rn(v.x * s, v.y * s);
                __half2 h23 = __floats2half2_rn(v.z * s, v.w * s);
                uint2 u;
                u.x = *(unsigned*)&h01;
                u.y = *(unsigned*)&h23;
                ((uint2*)g_bufH)[(size_t)row * 32 + (wc * 16 + c4)] = u;
            }
        }
        __syncwarp();
    }
}

// ---------------- aggregation: h[i] = fp16( relu(dinv[i]*(H[i] + sum H[nbr]) + b) ) ----------------
// one warp per node, 4 halfs (8B) per lane, fp32 accumulate (MLP_p1 = 1)
__global__ void k_agg(const float* __restrict__ bias) {
    int w = (blockIdx.x * blockDim.x + threadIdx.x) >> 5;
    int lane = threadIdx.x & 31;
    if (w >= NN) return;
    const uint2* g2 = (const uint2*)g_bufH;
    float4 acc;
    {
        uint2 u = g2[(size_t)w * 32 + lane];   // self loop term
        float2 f01 = __half22float2(*(__half2*)&u.x);
        float2 f23 = __half22float2(*(__half2*)&u.y);
        acc = make_float4(f01.x, f01.y, f23.x, f23.y);
    }
    int s = g_rowptr[w], e = g_rowptr[w + 1];
    for (int p = s; p < e; p++) {
        int j = g_col[p];
        uint2 u = g2[(size_t)j * 32 + lane];
        float2 f01 = __half22float2(*(__half2*)&u.x);
        float2 f23 = __half22float2(*(__half2*)&u.y);
        acc.x += f01.x; acc.y += f01.y; acc.z += f23.x; acc.w += f23.y;
    }
    float di = g_dinv[w];
    float4 b = ((const float4*)bias)[lane];
    __half2 h01 = __floats2half2_rn(fmaxf(fmaf(acc.x, di, b.x), 0.f),
                                    fmaxf(fmaf(acc.y, di, b.y), 0.f));
    __half2 h23 = __floats2half2_rn(fmaxf(fmaf(acc.z, di, b.z), 0.f),
                                    fmaxf(fmaf(acc.w, di, b.w), 0.f));
    uint2 u;
    u.x = *(unsigned*)&h01;
    u.y = *(unsigned*)&h23;
    ((uint2*)g_bufB16)[(size_t)w * 32 + lane] = u;
}

// ---------------- fused heads (fp16 wmma first layer, fp32 second layer) ----------------
// H1 = h @ [Wp1 | Wt1]  (192 cols, fp16 HMMA, fp32 acc); h read as fp16 (raw copy).
__global__ void k_head(const float* __restrict__ Wp1, const float* __restrict__ bp1,
                       const float* __restrict__ Wp2, const float* __restrict__ bp2,
                       const float* __restrict__ Wt1, const float* __restrict__ bt1,
                       const float* __restrict__ Wt2, const float* __restrict__ bt2,
                       float* __restrict__ out) {
    __shared__ __align__(16) char smemraw[49152];      // 48 KB
    __half* sA = (__half*)smemraw;                     // 128 x 40 halfs
    __half* sB = (__half*)(smemraw + 10240);           // 32 x 200 halfs (192 used)
    float*  stageF = (float*)smemraw;                  // epilogue: 4 x 16x192 fp32

    int tid  = threadIdx.x;
    int warp = tid >> 5, lane = tid & 31;
    int rowBase = blockIdx.x * 128;

    wmma::fragment<wmma::accumulator, 16, 16, 16, float> acc[12];
#pragma unroll
    for (int nt = 0; nt < 12; nt++) wmma::fill_fragment(acc[nt], 0.0f);

    for (int kc = 0; kc < 4; kc++) {
        __syncthreads();
        // stage A chunk: 128 rows x 32 cols of h (fp16 raw copy)
#pragma unroll
        for (int i = 0; i < 8; i++) {
            int idx = tid + 256 * i;             // 0..2047 half2
            int r = idx >> 4, c2 = idx & 15;
            int row = rowBase + r;
            unsigned u = 0;
            if (row < NN) u = ((const unsigned*)g_bufB16)[(size_t)row * 64 + kc * 16 + c2];
            *(unsigned*)&sA[r * 40 + c2 * 2] = u;
        }
        // stage B chunk: 32 rows x 192 cols = [Wp1 chunk | Wt1 chunk]
#pragma unroll
        for (int i = 0; i < 12; i++) {
            int idx = tid + 256 * i;             // 0..3071 half2
            int k = idx / 96, c2 = idx % 96;
            int kg = kc * 32 + k;
            float2 v;
            if (c2 < 64) v = ((const float2*)Wp1)[(size_t)kg * 64 + c2];
            else         v = ((const float2*)Wt1)[(size_t)kg * 32 + (c2 - 64)];
            *(__half2*)&sB[k * 200 + c2 * 2] = __floats2half2_rn(v.x, v.y);
        }
        __syncthreads();

#pragma unroll
        for (int k16 = 0; k16 < 2; k16++) {
            wmma::fragment<wmma::matrix_a, 16, 16, 16, __half, wmma::row_major> a;
            wmma::load_matrix_sync(a, sA + (warp * 16) * 40 + k16 * 16, 40);
#pragma unroll
            for (int nt = 0; nt < 12; nt++) {
                wmma::fragment<wmma::matrix_b, 16, 16, 16, __half, wmma::row_major> b;
                wmma::load_matrix_sync(b, sB + (k16 * 16) * 200 + nt * 16, 200);
                wmma::mma_sync(acc[nt], a, b, acc[nt]);
            }
        }
    }

    // per-lane second-layer constants
    float4 bP = ((const float4*)bp1)[lane];
    float2 bT = ((const float2*)bt1)[lane];
    float wp2a[4], wp2b[4];
#pragma unroll
    for (int i = 0; i < 4; i++) {
        wp2a[i] = Wp2[(lane * 4 + i) * 2];
        wp2b[i] = Wp2[(lane * 4 + i) * 2 + 1];
    }
    float wt2_0 = Wt2[lane * 2], wt2_1 = Wt2[lane * 2 + 1];
    float bpos0 = bp2[0], bpos1 = bp2[1], btime = bt2[0];

    __syncthreads();   // all mainloop reads of sA/sB complete before staging overwrite
    for (int batch = 0; batch < 2; batch++) {
        bool mine = (warp >> 2) == batch;
        if (mine) {
            float* st = stageF + (warp & 3) * 3072;   // 16 x 192
#pragma unroll
            for (int nt = 0; nt < 12; nt++)
                wmma::store_matrix_sync(st + nt * 16, acc[nt], 192, wmma::mem_row_major);
            __syncwarp();
#pragma unroll 2
            for (int r = 0; r < 16; r++) {
                int row = rowBase + warp * 16 + r;
                float4 hv = *(float4*)&st[r * 192 + lane * 4];
                float2 tvv = *(float2*)&st[r * 192 + 128 + lane * 2];
                float p0 = fmaxf(hv.x + bP.x, 0.f);
                float p1 = fmaxf(hv.y + bP.y, 0.f);
                float p2 = fmaxf(hv.z + bP.z, 0.f);
                float p3 = fmaxf(hv.w + bP.w, 0.f);
                float t0 = fmaxf(tvv.x + bT.x, 0.f);
                float t1 = fmaxf(tvv.y + bT.y, 0.f);
                float px = p0 * wp2a[0] + p1 * wp2a[1] + p2 * wp2a[2] + p3 * wp2a[3];
                float py = p0 * wp2b[0] + p1 * wp2b[1] + p2 * wp2b[2] + p3 * wp2b[3];
                float tv = t0 * wt2_0 + t1 * wt2_1;
#pragma unroll
                for (int off = 16; off; off >>= 1) {
                    px += __shfl_down_sync(0xffffffffu, px, off);
                    py += __shfl_down_sync(0xffffffffu, py, off);
                    tv += __shfl_down_sync(0xffffffffu, tv, off);
                }
                if (lane == 0 && row < NN) {
                    out[(size_t)row * 3 + 0] = px + bpos0;
                    out[(size_t)row * 3 + 1] = py + bpos1;
                    out[(size_t)row * 3 + 2] = tv + btime;
                }
            }
        }
        __syncthreads();
    }
}

// ---------------- launch ----------------
extern "C" void kernel_launch(void* const* d_in, const int* in_sizes, int n_in,
                              void* d_out, int out_size) {
    const float* x   = (const float*)d_in[0];
    const void*  ei  = d_in[1];
    const float* W1  = (const float*)d_in[2];  const float* b1  = (const float*)d_in[3];
    const float* W2  = (const float*)d_in[4];  const float* b2  = (const float*)d_in[5];
    const float* W3  = (const float*)d_in[6];  const float* b3  = (const float*)d_in[7];
    const float* Wp1 = (const float*)d_in[8];  const float* bp1 = (const float*)d_in[9];
    const float* Wp2 = (const float*)d_in[10]; const float* bp2 = (const float*)d_in[11];
    const float* Wt1 = (const float*)d_in[12]; const float* bt1 = (const float*)d_in[13];
    const float* Wt2 = (const float*)d_in[14]; const float* bt2 = (const float*)d_in[15];
    float* out = (float*)d_out;

    int nb256  = (NN + 255) / 256;
    int ebl    = (EE + 255) / 256;
    int nbScan = (NN + 1023) / 1024;

    k_zero_detect<<<nb256, 256>>>((const int*)ei);
    k_hist<<<ebl, 256>>>(ei);
    k_scan1<<<nbScan, 1024>>>();
    k_scan2<<<1, 1>>>(nbScan);
    k_scan3<<<nb256, 256>>>();
    k_fill<<<ebl, 256>>>(ei);

    int gemmGrid = (NN + 127) / 128;   // 782
    int aggGrid  = (NN + 7) / 8;       // 1 warp per node
    int headGrid = (NN + 127) / 128;   // 782

    k_gemm<<<gemmGrid, 256>>>(x, W1);
    k_agg <<<aggGrid, 256>>>(b1);
    k_gemm<<<gemmGrid, 256>>>(nullptr, W2);
    k_agg <<<aggGrid, 256>>>(b2);
    k_gemm<<<gemmGrid, 256>>>(nullptr, W3);
    k_agg <<<aggGrid, 256>>>(b3);

    k_head<<<headGrid, 256>>>(Wp1, bp1, Wp2, bp2, Wt1, bt1, Wt2, bt2, out);
}